// round 8
// baseline (speedup 1.0000x reference)
#include <cuda_runtime.h>
#include <cuda_bf16.h>
#include <cuda_fp16.h>
#include <cstdint>
#include <math.h>

// ---------------- static scratch (no allocs allowed) ----------------
#define NMAX 50176
#define EMAX 1700000

__device__ __half g_h1f[NMAX * 256];          // x @ W1 (fp16, for agg1 gather)
__device__ __nv_bfloat16 g_h1ah[NMAX * 256], g_h1al[NMAX * 256]; // layer1 out, bf16 split
__device__ __half g_h2f[NMAX * 40];           // fp16 for agg2 gather
__device__ float g_as1[NMAX * 4], g_ad1[NMAX * 4];
__device__ float g_as2[NMAX],     g_ad2[NMAX];
__device__ int   g_deg[NMAX], g_off[NMAX + 1], g_cur[NMAX];
__device__ int   g_csr[EMAX];
__device__ int   g_dstv[EMAX];
__device__ float g_w1[EMAX * 4];
__device__ float g_w2[EMAX];
__device__ int   g_is64;
// folded attention weight vectors
__device__ float g_ws1t[8 * 256];   // [j][k]: j=0..3 src heads, 4..7 dst heads
__device__ float g_ws2s[256], g_ws2d[256];
// bf16 split operands for tensor-core GEMMs
__device__ __nv_bfloat16 g_xh[NMAX * 256], g_xl[NMAX * 256];
__device__ __nv_bfloat16 g_wh[256 * 256],  g_wl[256 * 256];
__device__ __nv_bfloat16 g_w2h[256 * 64],  g_w2l[256 * 64];   // W2 padded 40->64

// ---------------- PTX helpers ----------------
__device__ __forceinline__ unsigned smem_u32(const void* p) {
    return (unsigned)__cvta_generic_to_shared(p);
}
__device__ __forceinline__ void ldsm_x4(unsigned addr, unsigned& r0, unsigned& r1, unsigned& r2, unsigned& r3) {
    asm volatile("ldmatrix.sync.aligned.m8n8.x4.shared.b16 {%0,%1,%2,%3},[%4];"
                 : "=r"(r0), "=r"(r1), "=r"(r2), "=r"(r3) : "r"(addr));
}
__device__ __forceinline__ void ldsm_x4t(unsigned addr, unsigned& r0, unsigned& r1, unsigned& r2, unsigned& r3) {
    asm volatile("ldmatrix.sync.aligned.m8n8.x4.trans.shared.b16 {%0,%1,%2,%3},[%4];"
                 : "=r"(r0), "=r"(r1), "=r"(r2), "=r"(r3) : "r"(addr));
}
__device__ __forceinline__ void mma_bf16(float* c, unsigned a0, unsigned a1, unsigned a2, unsigned a3,
                                         unsigned b0, unsigned b1) {
    asm volatile("mma.sync.aligned.m16n8k16.row.col.f32.bf16.bf16.f32 "
                 "{%0,%1,%2,%3},{%4,%5,%6,%7},{%8,%9},{%0,%1,%2,%3};"
                 : "+f"(c[0]), "+f"(c[1]), "+f"(c[2]), "+f"(c[3])
                 : "r"(a0), "r"(a1), "r"(a2), "r"(a3), "r"(b0), "r"(b1));
}

// ---------------- bf16 split conversion ----------------
__global__ void k_split(const float* __restrict__ src, __nv_bfloat16* __restrict__ hi,
                        __nv_bfloat16* __restrict__ lo, int n) {
    int i = blockIdx.x * blockDim.x + threadIdx.x;
    if (i >= n) return;
    float v = src[i];
    __nv_bfloat16 h = __float2bfloat16(v);
    hi[i] = h;
    lo[i] = __float2bfloat16(v - __bfloat162float(h));
}

__global__ void k_split_w2(const float* __restrict__ W2) {
    int i = blockIdx.x * blockDim.x + threadIdx.x;   // over 256*64
    if (i >= 256 * 64) return;
    int r = i >> 6, c = i & 63;
    float v = (c < 40) ? W2[r * 40 + c] : 0.f;
    __nv_bfloat16 h = __float2bfloat16(v);
    g_w2h[i] = h;
    g_w2l[i] = __float2bfloat16(v - __bfloat162float(h));
}

// ---------------- folded attention weights ----------------
// ws1t[h][k]   = sum_c W1[k, h*64+c] * att_src1[h*64+c]   (h=0..3)
// ws1t[4+h][k] = same with att_dst1
// ws2s[k] = sum_j W2[k,j]*att_src2[j] ; ws2d likewise
__global__ void k_wsprep(const float* __restrict__ W1,
                         const float* __restrict__ as1v, const float* __restrict__ ad1v,
                         const float* __restrict__ W2,
                         const float* __restrict__ as2v, const float* __restrict__ ad2v) {
    int t = blockIdx.x * blockDim.x + threadIdx.x;
    if (t < 256) {
        int k = t;
#pragma unroll
        for (int h = 0; h < 4; h++) {
            float s = 0.f, d = 0.f;
            for (int c = 0; c < 64; c++) {
                float w = W1[k * 256 + h * 64 + c];
                s = fmaf(w, as1v[h * 64 + c], s);
                d = fmaf(w, ad1v[h * 64 + c], d);
            }
            g_ws1t[h * 256 + k] = s;
            g_ws1t[(4 + h) * 256 + k] = d;
        }
    } else if (t < 512) {
        int k = t - 256;
        float s = 0.f, d = 0.f;
        for (int j = 0; j < 40; j++) {
            float w = W2[k * 40 + j];
            s = fmaf(w, as2v[j], s);
            d = fmaf(w, ad2v[j], d);
        }
        g_ws2s[k] = s;
        g_ws2d[k] = d;
    }
}

// ---------------- attn1 from x: as1/ad1 = x @ ws1t ----------------
__global__ void k_attn1x(const float* __restrict__ x, int M) {
    int w = (blockIdx.x * blockDim.x + threadIdx.x) >> 5;
    int lane = threadIdx.x & 31;
    if (w >= M) return;
    int j = lane >> 2;          // output 0..7
    int cb = lane & 3;          // channel block (64 ch)
    const float4* xp = (const float4*)&x[(size_t)w * 256 + cb * 64];
    const float4* wp = (const float4*)&g_ws1t[j * 256 + cb * 64];
    float acc = 0.f;
#pragma unroll
    for (int i = 0; i < 16; i++) {
        float4 xv = __ldg(&xp[i]);
        float4 wv = __ldg(&wp[i]);
        acc += xv.x * wv.x + xv.y * wv.y + xv.z * wv.z + xv.w * wv.w;
    }
    acc += __shfl_xor_sync(0xffffffffu, acc, 1);
    acc += __shfl_xor_sync(0xffffffffu, acc, 2);
    if (cb == 0) {
        if (j < 4) g_as1[w * 4 + j] = acc;
        else       g_ad1[w * 4 + (j - 4)] = acc;
    }
}

// ---------------- edge dtype detection (parallel) ----------------
__global__ void k_detect(const int* __restrict__ e32, int E) {
    int lane = threadIdx.x;
    int nz = 0;
    for (int i = lane; i < 64; i += 32)
        if (i < E) nz |= (e32[2 * i + 1] != 0);
    unsigned b = __ballot_sync(0xffffffffu, nz);
    if (lane == 0) g_is64 = (b == 0u);
}

__device__ __forceinline__ int edge_at(const void* edge, int is64, long long idx) {
    if (is64) return (int)((const long long*)edge)[idx];
    return ((const int*)edge)[idx];
}

// ---------------- CSR build ----------------
__global__ void k_zero_deg(int N) {
    int i = blockIdx.x * blockDim.x + threadIdx.x;
    if (i < N) g_deg[i] = 0;
}

__global__ void k_count(const void* __restrict__ edge, int E, int N) {
    int e = blockIdx.x * blockDim.x + threadIdx.x;
    int ET = E + N;
    if (e >= ET) return;
    int is64 = g_is64;
    int dst = (e < E) ? edge_at(edge, is64, (long long)E + e) : (e - E);
    atomicAdd(&g_deg[dst], 1);
}

__global__ void __launch_bounds__(1024) k_scan_fused(int N) {
    __shared__ int s[1024];
    int t = threadIdx.x;
    int chunk = (N + 1023) >> 10;
    int base = t * chunk;
    int sum = 0;
    for (int i = 0; i < chunk; i++) {
        int idx = base + i;
        if (idx < N) sum += g_deg[idx];
    }
    s[t] = sum;
    __syncthreads();
    for (int o = 1; o < 1024; o <<= 1) {
        int v = (t >= o) ? s[t - o] : 0;
        __syncthreads();
        s[t] += v;
        __syncthreads();
    }
    int run = s[t] - sum;
    for (int i = 0; i < chunk; i++) {
        int idx = base + i;
        if (idx < N) {
            g_off[idx] = run;
            g_cur[idx] = run;
            run += g_deg[idx];
        }
    }
    if (t == 1023) g_off[N] = s[1023];
}

__global__ void k_scatter(const void* __restrict__ edge, int E, int N) {
    int e = blockIdx.x * blockDim.x + threadIdx.x;
    int ET = E + N;
    if (e >= ET) return;
    int src, dst;
    if (e < E) {
        int is64 = g_is64;
        src = edge_at(edge, is64, e);
        dst = edge_at(edge, is64, (long long)E + e);
    } else {
        src = dst = e - E;
    }
    int pos = atomicAdd(&g_cur[dst], 1);
    g_csr[pos]  = src;
    g_dstv[pos] = dst;
}

// ---------------- GEMM1 (tensor core): 128x128 block tile, warp tile 32x64 ----------------
#define LDA 40
#define LDB1 136
__global__ void __launch_bounds__(256) k_gemm1_tc(int M) {
    __shared__ __nv_bfloat16 Ah[128 * LDA], Al[128 * LDA];
    __shared__ __nv_bfloat16 Bh[32 * LDB1], Bl[32 * LDB1];
    int tid = threadIdx.x;
    int warp = tid >> 5, lane = tid & 31;
    int wm = warp & 3, wn = warp >> 2;
    int row0 = blockIdx.y * 128, col0 = blockIdx.x * 128;

    float acc[2][8][4];
#pragma unroll
    for (int mi = 0; mi < 2; mi++)
#pragma unroll
        for (int ni = 0; ni < 8; ni++)
#pragma unroll
            for (int k = 0; k < 4; k++) acc[mi][ni][k] = 0.f;

    int lrow = lane & 15, lcb = lane >> 4;

    for (int kt = 0; kt < 256; kt += 32) {
        // A tile 128x32 hi+lo
#pragma unroll
        for (int i = 0; i < 2; i++) {
            int v = tid + i * 256;
            int r = v >> 2, cv = (v & 3) * 8;
            int gr = row0 + r;
            uint4 vh, vl;
            if (gr < M) {
                vh = *(const uint4*)&g_xh[(size_t)gr * 256 + kt + cv];
                vl = *(const uint4*)&g_xl[(size_t)gr * 256 + kt + cv];
            } else { vh = make_uint4(0,0,0,0); vl = vh; }
            *(uint4*)&Ah[r * LDA + cv] = vh;
            *(uint4*)&Al[r * LDA + cv] = vl;
        }
        // B tile 32x128 hi+lo
#pragma unroll
        for (int i = 0; i < 2; i++) {
            int v = tid + i * 256;
            int r = v >> 4, cv = (v & 15) * 8;
            *(uint4*)&Bh[r * LDB1 + cv] = *(const uint4*)&g_wh[(size_t)(kt + r) * 256 + col0 + cv];
            *(uint4*)&Bl[r * LDB1 + cv] = *(const uint4*)&g_wl[(size_t)(kt + r) * 256 + col0 + cv];
        }
        __syncthreads();

#pragma unroll
        for (int ks = 0; ks < 32; ks += 16) {
            unsigned ah[2][4], al[2][4], bh[4][4], bl[4][4];
#pragma unroll
            for (int mi = 0; mi < 2; mi++) {
                unsigned ad = smem_u32(&Ah[(wm * 32 + mi * 16 + lrow) * LDA + ks + lcb * 8]);
                ldsm_x4(ad, ah[mi][0], ah[mi][1], ah[mi][2], ah[mi][3]);
                unsigned ad2 = smem_u32(&Al[(wm * 32 + mi * 16 + lrow) * LDA + ks + lcb * 8]);
                ldsm_x4(ad2, al[mi][0], al[mi][1], al[mi][2], al[mi][3]);
            }
#pragma unroll
            for (int nj = 0; nj < 4; nj++) {
                unsigned bd = smem_u32(&Bh[(ks + lrow) * LDB1 + wn * 64 + nj * 16 + lcb * 8]);
                ldsm_x4t(bd, bh[nj][0], bh[nj][1], bh[nj][2], bh[nj][3]);
                unsigned bd2 = smem_u32(&Bl[(ks + lrow) * LDB1 + wn * 64 + nj * 16 + lcb * 8]);
                ldsm_x4t(bd2, bl[nj][0], bl[nj][1], bl[nj][2], bl[nj][3]);
            }
#pragma unroll
            for (int mi = 0; mi < 2; mi++)
#pragma unroll
                for (int ni = 0; ni < 8; ni++) {
                    int nj = ni >> 1, s2 = (ni & 1) * 2;
                    mma_bf16(acc[mi][ni], ah[mi][0], ah[mi][1], ah[mi][2], ah[mi][3],
                             bh[nj][s2], bh[nj][s2 + 1]);
                    mma_bf16(acc[mi][ni], ah[mi][0], ah[mi][1], ah[mi][2], ah[mi][3],
                             bl[nj][s2], bl[nj][s2 + 1]);
                    mma_bf16(acc[mi][ni], al[mi][0], al[mi][1], al[mi][2], al[mi][3],
                             bh[nj][s2], bh[nj][s2 + 1]);
                }
        }
        __syncthreads();
    }

    // epilogue: fp16 only
    int tr = lane >> 2, tc = (lane & 3) * 2;
#pragma unroll
    for (int mi = 0; mi < 2; mi++)
#pragma unroll
        for (int ni = 0; ni < 8; ni++) {
            int r = row0 + wm * 32 + mi * 16 + tr;
            int c = col0 + wn * 64 + ni * 8 + tc;
            if (r < M)
                *(__half2*)&g_h1f[(size_t)r * 256 + c] = __floats2half2_rn(acc[mi][ni][0], acc[mi][ni][1]);
            if (r + 8 < M)
                *(__half2*)&g_h1f[(size_t)(r + 8) * 256 + c] = __floats2half2_rn(acc[mi][ni][2], acc[mi][ni][3]);
        }
}

// ---------------- GEMM2 (tensor core): h2 = h1a @ W2pad (128x64 tile) ----------------
#define LDB 72
__global__ void __launch_bounds__(256) k_gemm2_tc(int M) {
    __shared__ __nv_bfloat16 Ah[128 * LDA], Al[128 * LDA];
    __shared__ __nv_bfloat16 Bh[32 * LDB],  Bl[32 * LDB];
    int tid = threadIdx.x;
    int warp = tid >> 5, lane = tid & 31;
    int wm = warp & 3, wn = warp >> 2;
    int row0 = blockIdx.x * 128;

    float acc[2][4][4];
#pragma unroll
    for (int mi = 0; mi < 2; mi++)
#pragma unroll
        for (int ni = 0; ni < 4; ni++)
#pragma unroll
            for (int k = 0; k < 4; k++) acc[mi][ni][k] = 0.f;

    int lrow = lane & 15, lcb = lane >> 4;

    for (int kt = 0; kt < 256; kt += 32) {
#pragma unroll
        for (int i = 0; i < 2; i++) {
            int v = tid + i * 256;
            int r = v >> 2, cv = (v & 3) * 8;
            int gr = row0 + r;
            uint4 vh, vl;
            if (gr < M) {
                vh = *(const uint4*)&g_h1ah[(size_t)gr * 256 + kt + cv];
                vl = *(const uint4*)&g_h1al[(size_t)gr * 256 + kt + cv];
            } else { vh = make_uint4(0,0,0,0); vl = vh; }
            *(uint4*)&Ah[r * LDA + cv] = vh;
            *(uint4*)&Al[r * LDA + cv] = vl;
        }
        {
            int r = tid >> 3, cv = (tid & 7) * 8;
            *(uint4*)&Bh[r * LDB + cv] = *(const uint4*)&g_w2h[(size_t)(kt + r) * 64 + cv];
            *(uint4*)&Bl[r * LDB + cv] = *(const uint4*)&g_w2l[(size_t)(kt + r) * 64 + cv];
        }
        __syncthreads();

#pragma unroll
        for (int ks = 0; ks < 32; ks += 16) {
            unsigned ah[2][4], al[2][4], bh[2][4], bl[2][4];
#pragma unroll
            for (int mi = 0; mi < 2; mi++) {
                unsigned ad = smem_u32(&Ah[(wm * 32 + mi * 16 + lrow) * LDA + ks + lcb * 8]);
                ldsm_x4(ad, ah[mi][0], ah[mi][1], ah[mi][2], ah[mi][3]);
                unsigned ad2 = smem_u32(&Al[(wm * 32 + mi * 16 + lrow) * LDA + ks + lcb * 8]);
                ldsm_x4(ad2, al[mi][0], al[mi][1], al[mi][2], al[mi][3]);
            }
#pragma unroll
            for (int nj = 0; nj < 2; nj++) {
                unsigned bd = smem_u32(&Bh[(ks + lrow) * LDB + wn * 32 + nj * 16 + lcb * 8]);
                ldsm_x4t(bd, bh[nj][0], bh[nj][1], bh[nj][2], bh[nj][3]);
                unsigned bd2 = smem_u32(&Bl[(ks + lrow) * LDB + wn * 32 + nj * 16 + lcb * 8]);
                ldsm_x4t(bd2, bl[nj][0], bl[nj][1], bl[nj][2], bl[nj][3]);
            }
#pragma unroll
            for (int mi = 0; mi < 2; mi++)
#pragma unroll
                for (int ni = 0; ni < 4; ni++) {
                    int nj = ni >> 1, s2 = (ni & 1) * 2;
                    mma_bf16(acc[mi][ni], ah[mi][0], ah[mi][1], ah[mi][2], ah[mi][3],
                             bh[nj][s2], bh[nj][s2 + 1]);
                    mma_bf16(acc[mi][ni], ah[mi][0], ah[mi][1], ah[mi][2], ah[mi][3],
                             bl[nj][s2], bl[nj][s2 + 1]);
                    mma_bf16(acc[mi][ni], al[mi][0], al[mi][1], al[mi][2], al[mi][3],
                             bh[nj][s2], bh[nj][s2 + 1]);
                }
        }
        __syncthreads();
    }

    int tr = lane >> 2, tc = (lane & 3) * 2;
#pragma unroll
    for (int mi = 0; mi < 2; mi++)
#pragma unroll
        for (int ni = 0; ni < 4; ni++) {
            int r = row0 + wm * 32 + mi * 16 + tr;
            int c = wn * 32 + ni * 8 + tc;
            if (c < 40) {
                if (r < M)
                    *(__half2*)&g_h2f[(size_t)r * 40 + c] = __floats2half2_rn(acc[mi][ni][0], acc[mi][ni][1]);
                if (r + 8 < M)
                    *(__half2*)&g_h2f[(size_t)(r + 8) * 40 + c] = __floats2half2_rn(acc[mi][ni][2], acc[mi][ni][3]);
            }
        }
}

// ---------------- edge weights layer1 ----------------
__global__ void k_edgew1(int ET) {
    int e = blockIdx.x * blockDim.x + threadIdx.x;
    if (e >= ET) return;
    int s = g_csr[e], d = g_dstv[e];
    float4 as = *(const float4*)&g_as1[s * 4];
    float4 ad = *(const float4*)&g_ad1[d * 4];
    float e0 = as.x + ad.x; e0 = e0 > 0.f ? e0 : 0.2f * e0;
    float e1 = as.y + ad.y; e1 = e1 > 0.f ? e1 : 0.2f * e1;
    float e2 = as.z + ad.z; e2 = e2 > 0.f ? e2 : 0.2f * e2;
    float e3 = as.w + ad.w; e3 = e3 > 0.f ? e3 : 0.2f * e3;
    float4 w = make_float4(__expf(e0), __expf(e1), __expf(e2), __expf(e3));
    *(float4*)&g_w1[e * 4] = w;
}

// ---------------- agg1: fp16 gather, softmax-agg + bias + ELU, bf16 split out, fused attn2 ----------------
__global__ void k_agg1(const float* __restrict__ bias, int M) {
    int w = (blockIdx.x * blockDim.x + threadIdx.x) >> 5;
    int lane = threadIdx.x & 31;
    if (w >= M) return;
    int start = g_off[w], end = g_off[w + 1];
    int hh = lane >> 3;
    int c0 = lane * 8;

    float acc[8] = {0.f, 0.f, 0.f, 0.f, 0.f, 0.f, 0.f, 0.f};
    float denom = 0.f;
    int j = start;
    for (; j + 1 < end; j += 2) {
        int s0 = g_csr[j], s1 = g_csr[j + 1];
        float w0 = g_w1[j * 4 + hh], w1 = g_w1[(j + 1) * 4 + hh];
        uint4 q0 = *(const uint4*)&g_h1f[(size_t)s0 * 256 + c0];
        uint4 q1 = *(const uint4*)&g_h1f[(size_t)s1 * 256 + c0];
        denom += w0 + w1;
        const __half2* a = (const __half2*)&q0;
        const __half2* b = (const __half2*)&q1;
#pragma unroll
        for (int k = 0; k < 4; k++) {
            float2 fa = __half22float2(a[k]);
            float2 fb = __half22float2(b[k]);
            acc[2*k]   = fmaf(w0, fa.x, acc[2*k]);   acc[2*k]   = fmaf(w1, fb.x, acc[2*k]);
            acc[2*k+1] = fmaf(w0, fa.y, acc[2*k+1]); acc[2*k+1] = fmaf(w1, fb.y, acc[2*k+1]);
        }
    }
    if (j < end) {
        int s0 = g_csr[j];
        float w0 = g_w1[j * 4 + hh];
        uint4 q0 = *(const uint4*)&g_h1f[(size_t)s0 * 256 + c0];
        denom += w0;
        const __half2* a = (const __half2*)&q0;
#pragma unroll
        for (int k = 0; k < 4; k++) {
            float2 fa = __half22float2(a[k]);
            acc[2*k]   = fmaf(w0, fa.x, acc[2*k]);
            acc[2*k+1] = fmaf(w0, fa.y, acc[2*k+1]);
        }
    }
    float inv = 1.f / denom;
    // ws2 coefficients for fused attn2
    float4 w2s0 = __ldg((const float4*)&g_ws2s[c0]);
    float4 w2s1 = __ldg((const float4*)&g_ws2s[c0 + 4]);
    float4 w2d0 = __ldg((const float4*)&g_ws2d[c0]);
    float4 w2d1 = __ldg((const float4*)&g_ws2d[c0 + 4]);
    float ws2s[8] = {w2s0.x, w2s0.y, w2s0.z, w2s0.w, w2s1.x, w2s1.y, w2s1.z, w2s1.w};
    float ws2d[8] = {w2d0.x, w2d0.y, w2d0.z, w2d0.w, w2d1.x, w2d1.y, w2d1.z, w2d1.w};

    __nv_bfloat16 hi8[8], lo8[8];
    float ps = 0.f, pd = 0.f;
#pragma unroll
    for (int k = 0; k < 8; k++) {
        float v = acc[k] * inv + bias[c0 + k];
        v = v > 0.f ? v : (__expf(v) - 1.f);   // ELU
        __nv_bfloat16 h = __float2bfloat16(v);
        hi8[k] = h;
        lo8[k] = __float2bfloat16(v - __bfloat162float(h));
        ps = fmaf(v, ws2s[k], ps);
        pd = fmaf(v, ws2d[k], pd);
    }
    *(uint4*)&g_h1ah[(size_t)w * 256 + c0] = *(const uint4*)hi8;
    *(uint4*)&g_h1al[(size_t)w * 256 + c0] = *(const uint4*)lo8;
#pragma unroll
    for (int o = 16; o >= 1; o >>= 1) {
        ps += __shfl_xor_sync(0xffffffffu, ps, o);
        pd += __shfl_xor_sync(0xffffffffu, pd, o);
    }
    if (lane == 0) { g_as2[w] = ps; g_ad2[w] = pd; }
}

// ---------------- edge weights layer2 ----------------
__global__ void k_edgew2(int ET) {
    int e = blockIdx.x * blockDim.x + threadIdx.x;
    if (e >= ET) return;
    int s = g_csr[e], d = g_dstv[e];
    float ev = g_as2[s] + g_ad2[d];
    ev = ev > 0.f ? ev : 0.2f * ev;
    g_w2[e] = __expf(ev);
}

// ---------------- agg2: fp16 gather, final output ----------------
__global__ void k_agg2(const float* __restrict__ b2, float* __restrict__ out, int M) {
    int w = (blockIdx.x * blockDim.x + threadIdx.x) >> 5;
    int lane = threadIdx.x & 31;
    if (w >= M) return;
    int start = g_off[w], end = g_off[w + 1];
    bool val = lane < 20;
    float denom = 0.f, acc0 = 0.f, acc1 = 0.f;
    int j = start;
    for (; j + 1 < end; j += 2) {
        int s0 = g_csr[j], s1 = g_csr[j + 1];
        float w0 = g_w2[j], w1 = g_w2[j + 1];
        float2 f0 = make_float2(0.f, 0.f), f1 = f0;
        if (val) {
            f0 = __half22float2(*(const __half2*)&g_h2f[(size_t)s0 * 40 + lane * 2]);
            f1 = __half22float2(*(const __half2*)&g_h2f[(size_t)s1 * 40 + lane * 2]);
        }
        denom += w0 + w1;
        acc0 = fmaf(w0, f0.x, acc0); acc0 = fmaf(w1, f1.x, acc0);
        acc1 = fmaf(w0, f0.y, acc1); acc1 = fmaf(w1, f1.y, acc1);
    }
    if (j < end) {
        int s0 = g_csr[j];
        float w0 = g_w2[j];
        float2 f0 = make_float2(0.f, 0.f);
        if (val) f0 = __half22float2(*(const __half2*)&g_h2f[(size_t)s0 * 40 + lane * 2]);
        denom += w0;
        acc0 = fmaf(w0, f0.x, acc0);
        acc1 = fmaf(w0, f0.y, acc1);
    }
    float inv = 1.f / denom;
    if (val) {
        out[(size_t)w * 40 + lane * 2]     = acc0 * inv + __ldg(&b2[lane * 2]);
        out[(size_t)w * 40 + lane * 2 + 1] = acc1 * inv + __ldg(&b2[lane * 2 + 1]);
    }
}

// ---------------- launch ----------------
extern "C" void kernel_launch(void* const* d_in, const int* in_sizes, int n_in,
                              void* d_out, int out_size) {
    const float* x    = (const float*)d_in[0];
    const void*  edge = (const void*)d_in[1];
    const float* W1   = (const float*)d_in[2];
    const float* as1  = (const float*)d_in[3];
    const float* ad1  = (const float*)d_in[4];
    const float* b1   = (const float*)d_in[5];
    const float* W2   = (const float*)d_in[6];
    const float* as2  = (const float*)d_in[7];
    const float* ad2  = (const float*)d_in[8];
    const float* b2   = (const float*)d_in[9];
    float* out = (float*)d_out;

    int N  = in_sizes[0] / 256;
    int E  = in_sizes[1] / 2;
    int ET = E + N;

    __nv_bfloat16 *xh, *xl, *wh, *wl;
    cudaGetSymbolAddress((void**)&xh, g_xh);
    cudaGetSymbolAddress((void**)&xl, g_xl);
    cudaGetSymbolAddress((void**)&wh, g_wh);
    cudaGetSymbolAddress((void**)&wl, g_wl);
    int nx = N * 256;

    // launch idx: 0,1 splits; 2 detect; 3 gemm1_tc (profiled slot)
    k_split<<<(nx + 255) / 256, 256>>>(x, xh, xl, nx);
    k_split<<<(65536 + 255) / 256, 256>>>(W1, wh, wl, 65536);
    k_detect<<<1, 32>>>((const int*)edge, E);
    dim3 g1(1, (N + 127) / 128);
    k_gemm1_tc<<<dim3(2, (N + 127) / 128), 256>>>(N);

    k_split_w2<<<(256 * 64 + 255) / 256, 256>>>(W2);
    k_wsprep<<<2, 256>>>(W1, as1, ad1, W2, as2, ad2);

    int warpGrid = (N * 32 + 255) / 256;
    k_attn1x<<<warpGrid, 256>>>(x, N);

    // CSR build
    k_zero_deg<<<(N + 255) / 256, 256>>>(N);
    k_count<<<(ET + 255) / 256, 256>>>(edge, E, N);
    k_scan_fused<<<1, 1024>>>(N);
    k_scatter<<<(ET + 255) / 256, 256>>>(edge, E, N);

    // Layer 1
    k_edgew1<<<(ET + 255) / 256, 256>>>(ET);
    k_agg1<<<warpGrid, 256>>>(b1, N);

    // Layer 2
    k_gemm2_tc<<<(N + 127) / 128, 256>>>(N);
    k_edgew2<<<(ET + 255) / 256, 256>>>(ET);
    k_agg2<<<warpGrid, 256>>>(b2, out, N);
}

// round 9
// speedup vs baseline: 1.3850x; 1.3850x over previous
#include <cuda_runtime.h>
#include <cuda_bf16.h>
#include <cuda_fp16.h>
#include <cstdint>
#include <math.h>

// ---------------- static scratch (no allocs allowed) ----------------
#define NMAX 50176
#define EMAX 1700000

__device__ float g_h1 [NMAX * 256];           // x @ W1 (fp32, for attn1)
__device__ __half g_h1f[NMAX * 256];          // x @ W1 (fp16, for agg1 gather)
__device__ __nv_bfloat16 g_h1ah[NMAX * 256], g_h1al[NMAX * 256]; // layer1 out, bf16 split
__device__ float g_h2 [NMAX * 40];            // h1a @ W2 (fp32, for attn2)
__device__ __half g_h2f[NMAX * 40];           // fp16 for agg2 gather
__device__ float g_as1[NMAX * 4], g_ad1[NMAX * 4];
__device__ float g_as2[NMAX],     g_ad2[NMAX];
__device__ int   g_deg[NMAX], g_off[NMAX + 1], g_cur[NMAX];
__device__ int   g_csr[EMAX];
__device__ int   g_dstv[EMAX];
__device__ float g_w1[EMAX * 4];
__device__ float g_w2[EMAX];
__device__ int   g_is64;
// bf16 split operands for tensor-core GEMMs
__device__ __nv_bfloat16 g_xh[NMAX * 256], g_xl[NMAX * 256];
__device__ __nv_bfloat16 g_wh[256 * 256],  g_wl[256 * 256];
__device__ __nv_bfloat16 g_w2h[256 * 64],  g_w2l[256 * 64];   // W2 padded 40->64

// ---------------- PTX helpers ----------------
__device__ __forceinline__ unsigned smem_u32(const void* p) {
    return (unsigned)__cvta_generic_to_shared(p);
}
__device__ __forceinline__ void ldsm_x4(unsigned addr, unsigned& r0, unsigned& r1, unsigned& r2, unsigned& r3) {
    asm volatile("ldmatrix.sync.aligned.m8n8.x4.shared.b16 {%0,%1,%2,%3},[%4];"
                 : "=r"(r0), "=r"(r1), "=r"(r2), "=r"(r3) : "r"(addr));
}
__device__ __forceinline__ void ldsm_x4t(unsigned addr, unsigned& r0, unsigned& r1, unsigned& r2, unsigned& r3) {
    asm volatile("ldmatrix.sync.aligned.m8n8.x4.trans.shared.b16 {%0,%1,%2,%3},[%4];"
                 : "=r"(r0), "=r"(r1), "=r"(r2), "=r"(r3) : "r"(addr));
}
__device__ __forceinline__ void mma_bf16(float* c, unsigned a0, unsigned a1, unsigned a2, unsigned a3,
                                         unsigned b0, unsigned b1) {
    asm volatile("mma.sync.aligned.m16n8k16.row.col.f32.bf16.bf16.f32 "
                 "{%0,%1,%2,%3},{%4,%5,%6,%7},{%8,%9},{%0,%1,%2,%3};"
                 : "+f"(c[0]), "+f"(c[1]), "+f"(c[2]), "+f"(c[3])
                 : "r"(a0), "r"(a1), "r"(a2), "r"(a3), "r"(b0), "r"(b1));
}

// ---------------- bf16 split conversion ----------------
__global__ void k_split(const float* __restrict__ src, __nv_bfloat16* __restrict__ hi,
                        __nv_bfloat16* __restrict__ lo, int n) {
    int i = blockIdx.x * blockDim.x + threadIdx.x;
    if (i >= n) return;
    float v = src[i];
    __nv_bfloat16 h = __float2bfloat16(v);
    hi[i] = h;
    lo[i] = __float2bfloat16(v - __bfloat162float(h));
}

__global__ void k_split_w2(const float* __restrict__ W2) {
    int i = blockIdx.x * blockDim.x + threadIdx.x;   // over 256*64
    if (i >= 256 * 64) return;
    int r = i >> 6, c = i & 63;
    float v = (c < 40) ? W2[r * 40 + c] : 0.f;
    __nv_bfloat16 h = __float2bfloat16(v);
    g_w2h[i] = h;
    g_w2l[i] = __float2bfloat16(v - __bfloat162float(h));
}

// ---------------- edge dtype detection (parallel) ----------------
__global__ void k_detect(const int* __restrict__ e32, int E) {
    int lane = threadIdx.x;
    int nz = 0;
    for (int i = lane; i < 64; i += 32)
        if (i < E) nz |= (e32[2 * i + 1] != 0);
    unsigned b = __ballot_sync(0xffffffffu, nz);
    if (lane == 0) g_is64 = (b == 0u);
}

__device__ __forceinline__ int edge_at(const void* edge, int is64, long long idx) {
    if (is64) return (int)((const long long*)edge)[idx];
    return ((const int*)edge)[idx];
}

// ---------------- CSR build ----------------
__global__ void k_zero_deg(int N) {
    int i = blockIdx.x * blockDim.x + threadIdx.x;
    if (i < N) g_deg[i] = 0;
}

__global__ void k_count(const void* __restrict__ edge, int E, int N) {
    int e = blockIdx.x * blockDim.x + threadIdx.x;
    int ET = E + N;
    if (e >= ET) return;
    int is64 = g_is64;
    int dst = (e < E) ? edge_at(edge, is64, (long long)E + e) : (e - E);
    atomicAdd(&g_deg[dst], 1);
}

__global__ void __launch_bounds__(1024) k_scan_fused(int N) {
    __shared__ int s[1024];
    int t = threadIdx.x;
    int chunk = (N + 1023) >> 10;
    int base = t * chunk;
    int sum = 0;
    for (int i = 0; i < chunk; i++) {
        int idx = base + i;
        if (idx < N) sum += g_deg[idx];
    }
    s[t] = sum;
    __syncthreads();
    for (int o = 1; o < 1024; o <<= 1) {
        int v = (t >= o) ? s[t - o] : 0;
        __syncthreads();
        s[t] += v;
        __syncthreads();
    }
    int run = s[t] - sum;
    for (int i = 0; i < chunk; i++) {
        int idx = base + i;
        if (idx < N) {
            g_off[idx] = run;
            g_cur[idx] = run;
            run += g_deg[idx];
        }
    }
    if (t == 1023) g_off[N] = s[1023];
}

__global__ void k_scatter(const void* __restrict__ edge, int E, int N) {
    int e = blockIdx.x * blockDim.x + threadIdx.x;
    int ET = E + N;
    if (e >= ET) return;
    int src, dst;
    if (e < E) {
        int is64 = g_is64;
        src = edge_at(edge, is64, e);
        dst = edge_at(edge, is64, (long long)E + e);
    } else {
        src = dst = e - E;
    }
    int pos = atomicAdd(&g_cur[dst], 1);
    g_csr[pos]  = src;
    g_dstv[pos] = dst;
}

// ---------------- GEMM1 (tensor core): 128x128 block tile, 2 CTAs/SM ----------------
#define LDA 40
#define LDB1 136
__global__ void __launch_bounds__(256, 2) k_gemm1_tc(int M) {
    __shared__ __nv_bfloat16 Ah[128 * LDA], Al[128 * LDA];
    __shared__ __nv_bfloat16 Bh[32 * LDB1], Bl[32 * LDB1];
    int tid = threadIdx.x;
    int warp = tid >> 5, lane = tid & 31;
    int wm = warp & 3, wn = warp >> 2;
    int row0 = blockIdx.y * 128, col0 = blockIdx.x * 128;

    float acc[2][8][4];
#pragma unroll
    for (int mi = 0; mi < 2; mi++)
#pragma unroll
        for (int ni = 0; ni < 8; ni++)
#pragma unroll
            for (int k = 0; k < 4; k++) acc[mi][ni][k] = 0.f;

    int lrow = lane & 15, lcb = lane >> 4;

    for (int kt = 0; kt < 256; kt += 32) {
        // A tile 128x32 hi+lo
#pragma unroll
        for (int i = 0; i < 2; i++) {
            int v = tid + i * 256;
            int r = v >> 2, cv = (v & 3) * 8;
            int gr = row0 + r;
            uint4 vh, vl;
            if (gr < M) {
                vh = *(const uint4*)&g_xh[(size_t)gr * 256 + kt + cv];
                vl = *(const uint4*)&g_xl[(size_t)gr * 256 + kt + cv];
            } else { vh = make_uint4(0,0,0,0); vl = vh; }
            *(uint4*)&Ah[r * LDA + cv] = vh;
            *(uint4*)&Al[r * LDA + cv] = vl;
        }
        // B tile 32x128 hi+lo
#pragma unroll
        for (int i = 0; i < 2; i++) {
            int v = tid + i * 256;
            int r = v >> 4, cv = (v & 15) * 8;
            *(uint4*)&Bh[r * LDB1 + cv] = *(const uint4*)&g_wh[(size_t)(kt + r) * 256 + col0 + cv];
            *(uint4*)&Bl[r * LDB1 + cv] = *(const uint4*)&g_wl[(size_t)(kt + r) * 256 + col0 + cv];
        }
        __syncthreads();

#pragma unroll
        for (int ks = 0; ks < 32; ks += 16) {
            unsigned ah[2][4], al[2][4], bh[4][4], bl[4][4];
#pragma unroll
            for (int mi = 0; mi < 2; mi++) {
                unsigned ad = smem_u32(&Ah[(wm * 32 + mi * 16 + lrow) * LDA + ks + lcb * 8]);
                ldsm_x4(ad, ah[mi][0], ah[mi][1], ah[mi][2], ah[mi][3]);
                unsigned ad2 = smem_u32(&Al[(wm * 32 + mi * 16 + lrow) * LDA + ks + lcb * 8]);
                ldsm_x4(ad2, al[mi][0], al[mi][1], al[mi][2], al[mi][3]);
            }
#pragma unroll
            for (int nj = 0; nj < 4; nj++) {
                unsigned bd = smem_u32(&Bh[(ks + lrow) * LDB1 + wn * 64 + nj * 16 + lcb * 8]);
                ldsm_x4t(bd, bh[nj][0], bh[nj][1], bh[nj][2], bh[nj][3]);
                unsigned bd2 = smem_u32(&Bl[(ks + lrow) * LDB1 + wn * 64 + nj * 16 + lcb * 8]);
                ldsm_x4t(bd2, bl[nj][0], bl[nj][1], bl[nj][2], bl[nj][3]);
            }
#pragma unroll
            for (int mi = 0; mi < 2; mi++)
#pragma unroll
                for (int ni = 0; ni < 8; ni++) {
                    int nj = ni >> 1, s2 = (ni & 1) * 2;
                    mma_bf16(acc[mi][ni], ah[mi][0], ah[mi][1], ah[mi][2], ah[mi][3],
                             bh[nj][s2], bh[nj][s2 + 1]);
                    mma_bf16(acc[mi][ni], ah[mi][0], ah[mi][1], ah[mi][2], ah[mi][3],
                             bl[nj][s2], bl[nj][s2 + 1]);
                    mma_bf16(acc[mi][ni], al[mi][0], al[mi][1], al[mi][2], al[mi][3],
                             bh[nj][s2], bh[nj][s2 + 1]);
                }
        }
        __syncthreads();
    }

    // epilogue: fp32 (for attn1) + fp16 (for agg1 gather)
    int tr = lane >> 2, tc = (lane & 3) * 2;
#pragma unroll
    for (int mi = 0; mi < 2; mi++)
#pragma unroll
        for (int ni = 0; ni < 8; ni++) {
            int r = row0 + wm * 32 + mi * 16 + tr;
            int c = col0 + wn * 64 + ni * 8 + tc;
            if (r < M) {
                g_h1[(size_t)r * 256 + c]     = acc[mi][ni][0];
                g_h1[(size_t)r * 256 + c + 1] = acc[mi][ni][1];
                *(__half2*)&g_h1f[(size_t)r * 256 + c] = __floats2half2_rn(acc[mi][ni][0], acc[mi][ni][1]);
            }
            if (r + 8 < M) {
                g_h1[(size_t)(r + 8) * 256 + c]     = acc[mi][ni][2];
                g_h1[(size_t)(r + 8) * 256 + c + 1] = acc[mi][ni][3];
                *(__half2*)&g_h1f[(size_t)(r + 8) * 256 + c] = __floats2half2_rn(acc[mi][ni][2], acc[mi][ni][3]);
            }
        }
}

// ---------------- GEMM2 (tensor core): h2 = h1a @ W2pad ----------------
#define LDB 72
__global__ void __launch_bounds__(256) k_gemm2_tc(int M) {
    __shared__ __nv_bfloat16 Ah[128 * LDA], Al[128 * LDA];
    __shared__ __nv_bfloat16 Bh[32 * LDB],  Bl[32 * LDB];
    int tid = threadIdx.x;
    int warp = tid >> 5, lane = tid & 31;
    int wm = warp & 3, wn = warp >> 2;
    int row0 = blockIdx.x * 128;

    float acc[2][4][4];
#pragma unroll
    for (int mi = 0; mi < 2; mi++)
#pragma unroll
        for (int ni = 0; ni < 4; ni++)
#pragma unroll
            for (int k = 0; k < 4; k++) acc[mi][ni][k] = 0.f;

    int lrow = lane & 15, lcb = lane >> 4;

    for (int kt = 0; kt < 256; kt += 32) {
#pragma unroll
        for (int i = 0; i < 2; i++) {
            int v = tid + i * 256;
            int r = v >> 2, cv = (v & 3) * 8;
            int gr = row0 + r;
            uint4 vh, vl;
            if (gr < M) {
                vh = *(const uint4*)&g_h1ah[(size_t)gr * 256 + kt + cv];
                vl = *(const uint4*)&g_h1al[(size_t)gr * 256 + kt + cv];
            } else { vh = make_uint4(0,0,0,0); vl = vh; }
            *(uint4*)&Ah[r * LDA + cv] = vh;
            *(uint4*)&Al[r * LDA + cv] = vl;
        }
        {
            int r = tid >> 3, cv = (tid & 7) * 8;
            *(uint4*)&Bh[r * LDB + cv] = *(const uint4*)&g_w2h[(size_t)(kt + r) * 64 + cv];
            *(uint4*)&Bl[r * LDB + cv] = *(const uint4*)&g_w2l[(size_t)(kt + r) * 64 + cv];
        }
        __syncthreads();

#pragma unroll
        for (int ks = 0; ks < 32; ks += 16) {
            unsigned ah[2][4], al[2][4], bh[2][4], bl[2][4];
#pragma unroll
            for (int mi = 0; mi < 2; mi++) {
                unsigned ad = smem_u32(&Ah[(wm * 32 + mi * 16 + lrow) * LDA + ks + lcb * 8]);
                ldsm_x4(ad, ah[mi][0], ah[mi][1], ah[mi][2], ah[mi][3]);
                unsigned ad2 = smem_u32(&Al[(wm * 32 + mi * 16 + lrow) * LDA + ks + lcb * 8]);
                ldsm_x4(ad2, al[mi][0], al[mi][1], al[mi][2], al[mi][3]);
            }
#pragma unroll
            for (int nj = 0; nj < 2; nj++) {
                unsigned bd = smem_u32(&Bh[(ks + lrow) * LDB + wn * 32 + nj * 16 + lcb * 8]);
                ldsm_x4t(bd, bh[nj][0], bh[nj][1], bh[nj][2], bh[nj][3]);
                unsigned bd2 = smem_u32(&Bl[(ks + lrow) * LDB + wn * 32 + nj * 16 + lcb * 8]);
                ldsm_x4t(bd2, bl[nj][0], bl[nj][1], bl[nj][2], bl[nj][3]);
            }
#pragma unroll
            for (int mi = 0; mi < 2; mi++)
#pragma unroll
                for (int ni = 0; ni < 4; ni++) {
                    int nj = ni >> 1, s2 = (ni & 1) * 2;
                    mma_bf16(acc[mi][ni], ah[mi][0], ah[mi][1], ah[mi][2], ah[mi][3],
                             bh[nj][s2], bh[nj][s2 + 1]);
                    mma_bf16(acc[mi][ni], ah[mi][0], ah[mi][1], ah[mi][2], ah[mi][3],
                             bl[nj][s2], bl[nj][s2 + 1]);
                    mma_bf16(acc[mi][ni], al[mi][0], al[mi][1], al[mi][2], al[mi][3],
                             bh[nj][s2], bh[nj][s2 + 1]);
                }
        }
        __syncthreads();
    }

    int tr = lane >> 2, tc = (lane & 3) * 2;
#pragma unroll
    for (int mi = 0; mi < 2; mi++)
#pragma unroll
        for (int ni = 0; ni < 4; ni++) {
            int r = row0 + wm * 32 + mi * 16 + tr;
            int c = wn * 32 + ni * 8 + tc;
            if (c < 40) {
                if (r < M) {
                    g_h2[(size_t)r * 40 + c]     = acc[mi][ni][0];
                    g_h2[(size_t)r * 40 + c + 1] = acc[mi][ni][1];
                    *(__half2*)&g_h2f[(size_t)r * 40 + c] = __floats2half2_rn(acc[mi][ni][0], acc[mi][ni][1]);
                }
                if (r + 8 < M) {
                    g_h2[(size_t)(r + 8) * 40 + c]     = acc[mi][ni][2];
                    g_h2[(size_t)(r + 8) * 40 + c + 1] = acc[mi][ni][3];
                    *(__half2*)&g_h2f[(size_t)(r + 8) * 40 + c] = __floats2half2_rn(acc[mi][ni][2], acc[mi][ni][3]);
                }
            }
        }
}

// ---------------- attn1 ----------------
__global__ void k_attn1(const float* __restrict__ att_s, const float* __restrict__ att_d, int M) {
    int w = (blockIdx.x * blockDim.x + threadIdx.x) >> 5;
    int lane = threadIdx.x & 31;
    if (w >= M) return;
    int c0 = lane * 8;
    const float4* hp = (const float4*)&g_h1[(size_t)w * 256 + c0];
    float4 h0 = hp[0], h1v = hp[1];
    const float4* sp = (const float4*)&att_s[c0];
    const float4* dp = (const float4*)&att_d[c0];
    float4 s0 = sp[0], s1 = sp[1];
    float4 d0 = dp[0], d1 = dp[1];
    float ps = h0.x*s0.x + h0.y*s0.y + h0.z*s0.z + h0.w*s0.w
             + h1v.x*s1.x + h1v.y*s1.y + h1v.z*s1.z + h1v.w*s1.w;
    float pd = h0.x*d0.x + h0.y*d0.y + h0.z*d0.z + h0.w*d0.w
             + h1v.x*d1.x + h1v.y*d1.y + h1v.z*d1.z + h1v.w*d1.w;
#pragma unroll
    for (int o = 4; o >= 1; o >>= 1) {
        ps += __shfl_xor_sync(0xffffffffu, ps, o);
        pd += __shfl_xor_sync(0xffffffffu, pd, o);
    }
    if ((lane & 7) == 0) {
        int hh = lane >> 3;
        g_as1[w * 4 + hh] = ps;
        g_ad1[w * 4 + hh] = pd;
    }
}

// ---------------- edge weights layer1 ----------------
__global__ void k_edgew1(int ET) {
    int e = blockIdx.x * blockDim.x + threadIdx.x;
    if (e >= ET) return;
    int s = g_csr[e], d = g_dstv[e];
    float4 as = *(const float4*)&g_as1[s * 4];
    float4 ad = *(const float4*)&g_ad1[d * 4];
    float e0 = as.x + ad.x; e0 = e0 > 0.f ? e0 : 0.2f * e0;
    float e1 = as.y + ad.y; e1 = e1 > 0.f ? e1 : 0.2f * e1;
    float e2 = as.z + ad.z; e2 = e2 > 0.f ? e2 : 0.2f * e2;
    float e3 = as.w + ad.w; e3 = e3 > 0.f ? e3 : 0.2f * e3;
    float4 w = make_float4(__expf(e0), __expf(e1), __expf(e2), __expf(e3));
    *(float4*)&g_w1[e * 4] = w;
}

// ---------------- agg1: fp16 gather, weighted sum / denom, + bias + ELU, bf16-split out ----------------
__global__ void k_agg1(const float* __restrict__ bias, int M) {
    int w = (blockIdx.x * blockDim.x + threadIdx.x) >> 5;
    int lane = threadIdx.x & 31;
    if (w >= M) return;
    int start = g_off[w], end = g_off[w + 1];
    int hh = lane >> 3;
    int c0 = lane * 8;

    float acc[8] = {0.f, 0.f, 0.f, 0.f, 0.f, 0.f, 0.f, 0.f};
    float denom = 0.f;
    int j = start;
    for (; j + 1 < end; j += 2) {
        int s0 = g_csr[j], s1 = g_csr[j + 1];
        float w0 = g_w1[j * 4 + hh], w1 = g_w1[(j + 1) * 4 + hh];
        uint4 q0 = *(const uint4*)&g_h1f[(size_t)s0 * 256 + c0];
        uint4 q1 = *(const uint4*)&g_h1f[(size_t)s1 * 256 + c0];
        denom += w0 + w1;
        const __half2* a = (const __half2*)&q0;
        const __half2* b = (const __half2*)&q1;
#pragma unroll
        for (int k = 0; k < 4; k++) {
            float2 fa = __half22float2(a[k]);
            float2 fb = __half22float2(b[k]);
            acc[2*k]   = fmaf(w0, fa.x, acc[2*k]);   acc[2*k]   = fmaf(w1, fb.x, acc[2*k]);
            acc[2*k+1] = fmaf(w0, fa.y, acc[2*k+1]); acc[2*k+1] = fmaf(w1, fb.y, acc[2*k+1]);
        }
    }
    if (j < end) {
        int s0 = g_csr[j];
        float w0 = g_w1[j * 4 + hh];
        uint4 q0 = *(const uint4*)&g_h1f[(size_t)s0 * 256 + c0];
        denom += w0;
        const __half2* a = (const __half2*)&q0;
#pragma unroll
        for (int k = 0; k < 4; k++) {
            float2 fa = __half22float2(a[k]);
            acc[2*k]   = fmaf(w0, fa.x, acc[2*k]);
            acc[2*k+1] = fmaf(w0, fa.y, acc[2*k+1]);
        }
    }
    float inv = 1.f / denom;
    __nv_bfloat16 hi8[8], lo8[8];
#pragma unroll
    for (int k = 0; k < 8; k++) {
        float v = acc[k] * inv + bias[c0 + k];
        v = v > 0.f ? v : (__expf(v) - 1.f);   // ELU
        __nv_bfloat16 h = __float2bfloat16(v);
        hi8[k] = h;
        lo8[k] = __float2bfloat16(v - __bfloat162float(h));
    }
    *(uint4*)&g_h1ah[(size_t)w * 256 + c0] = *(const uint4*)hi8;
    *(uint4*)&g_h1al[(size_t)w * 256 + c0] = *(const uint4*)lo8;
}

// ---------------- attn2 ----------------
__global__ void k_attn2(const float* __restrict__ att_s, const float* __restrict__ att_d, int M) {
    int w = (blockIdx.x * blockDim.x + threadIdx.x) >> 5;
    int lane = threadIdx.x & 31;
    if (w >= M) return;
    const float* h = &g_h2[(size_t)w * 40];
    float ps = h[lane] * __ldg(&att_s[lane]);
    float pd = h[lane] * __ldg(&att_d[lane]);
    if (lane < 8) {
        ps += h[32 + lane] * __ldg(&att_s[32 + lane]);
        pd += h[32 + lane] * __ldg(&att_d[32 + lane]);
    }
#pragma unroll
    for (int o = 16; o >= 1; o >>= 1) {
        ps += __shfl_xor_sync(0xffffffffu, ps, o);
        pd += __shfl_xor_sync(0xffffffffu, pd, o);
    }
    if (lane == 0) { g_as2[w] = ps; g_ad2[w] = pd; }
}

// ---------------- edge weights layer2 ----------------
__global__ void k_edgew2(int ET) {
    int e = blockIdx.x * blockDim.x + threadIdx.x;
    if (e >= ET) return;
    int s = g_csr[e], d = g_dstv[e];
    float ev = g_as2[s] + g_ad2[d];
    ev = ev > 0.f ? ev : 0.2f * ev;
    g_w2[e] = __expf(ev);
}

// ---------------- agg2: fp16 gather, final output ----------------
__global__ void k_agg2(const float* __restrict__ b2, float* __restrict__ out, int M) {
    int w = (blockIdx.x * blockDim.x + threadIdx.x) >> 5;
    int lane = threadIdx.x & 31;
    if (w >= M) return;
    int start = g_off[w], end = g_off[w + 1];
    bool val = lane < 20;
    float denom = 0.f, acc0 = 0.f, acc1 = 0.f;
    int j = start;
    for (; j + 1 < end; j += 2) {
        int s0 = g_csr[j], s1 = g_csr[j + 1];
        float w0 = g_w2[j], w1 = g_w2[j + 1];
        float2 f0 = make_float2(0.f, 0.f), f1 = f0;
        if (val) {
            f0 = __half22float2(*(const __half2*)&g_h2f[(size_t)s0 * 40 + lane * 2]);
            f1 = __half22float2(*(const __half2*)&g_h2f[(size_t)s1 * 40 + lane * 2]);
        }
        denom += w0 + w1;
        acc0 = fmaf(w0, f0.x, acc0); acc0 = fmaf(w1, f1.x, acc0);
        acc1 = fmaf(w0, f0.y, acc1); acc1 = fmaf(w1, f1.y, acc1);
    }
    if (j < end) {
        int s0 = g_csr[j];
        float w0 = g_w2[j];
        float2 f0 = make_float2(0.f, 0.f);
        if (val) f0 = __half22float2(*(const __half2*)&g_h2f[(size_t)s0 * 40 + lane * 2]);
        denom += w0;
        acc0 = fmaf(w0, f0.x, acc0);
        acc1 = fmaf(w0, f0.y, acc1);
    }
    float inv = 1.f / denom;
    if (val) {
        out[(size_t)w * 40 + lane * 2]     = acc0 * inv + __ldg(&b2[lane * 2]);
        out[(size_t)w * 40 + lane * 2 + 1] = acc1 * inv + __ldg(&b2[lane * 2 + 1]);
    }
}

// ---------------- launch ----------------
extern "C" void kernel_launch(void* const* d_in, const int* in_sizes, int n_in,
                              void* d_out, int out_size) {
    const float* x    = (const float*)d_in[0];
    const void*  edge = (const void*)d_in[1];
    const float* W1   = (const float*)d_in[2];
    const float* as1  = (const float*)d_in[3];
    const float* ad1  = (const float*)d_in[4];
    const float* b1   = (const float*)d_in[5];
    const float* W2   = (const float*)d_in[6];
    const float* as2  = (const float*)d_in[7];
    const float* ad2  = (const float*)d_in[8];
    const float* b2   = (const float*)d_in[9];
    float* out = (float*)d_out;

    int N  = in_sizes[0] / 256;
    int E  = in_sizes[1] / 2;
    int ET = E + N;

    __nv_bfloat16 *xh, *xl, *wh, *wl;
    cudaGetSymbolAddress((void**)&xh, g_xh);
    cudaGetSymbolAddress((void**)&xl, g_xl);
    cudaGetSymbolAddress((void**)&wh, g_wh);
    cudaGetSymbolAddress((void**)&wl, g_wl);
    int nx = N * 256;

    // launch idx: 0,1 splits; 2 detect; 3 gemm1_tc (profiled slot)
    k_split<<<(nx + 255) / 256, 256>>>(x, xh, xl, nx);
    k_split<<<(65536 + 255) / 256, 256>>>(W1, wh, wl, 65536);
    k_detect<<<1, 32>>>((const int*)edge, E);
    k_gemm1_tc<<<dim3(2, (N + 127) / 128), 256>>>(N);

    k_split_w2<<<(256 * 64 + 255) / 256, 256>>>(W2);

    // CSR build
    k_zero_deg<<<(N + 255) / 256, 256>>>(N);
    k_count<<<(ET + 255) / 256, 256>>>(edge, E, N);
    k_scan_fused<<<1, 1024>>>(N);
    k_scatter<<<(ET + 255) / 256, 256>>>(edge, E, N);

    // Layer 1
    int warpGrid = (N * 32 + 255) / 256;
    k_attn1<<<warpGrid, 256>>>(as1, ad1, N);
    k_edgew1<<<(ET + 255) / 256, 256>>>(ET);
    k_agg1<<<warpGrid, 256>>>(b1, N);

    // Layer 2
    k_gemm2_tc<<<(N + 127) / 128, 256>>>(N);
    k_attn2<<<warpGrid, 256>>>(as2, ad2, N);
    k_edgew2<<<(ET + 255) / 256, 256>>>(ET);
    k_agg2<<<warpGrid, 256>>>(b2, out, N);
}

// round 10
// speedup vs baseline: 1.4578x; 1.0525x over previous
#include <cuda_runtime.h>
#include <cuda_bf16.h>
#include <cuda_fp16.h>
#include <cstdint>
#include <math.h>

// ---------------- static scratch (no allocs allowed) ----------------
#define NMAX 50176
#define EMAX 1700000

__device__ __half g_h1f[NMAX * 256];          // x @ W1 (fp16, for agg1 gather)
__device__ __nv_bfloat16 g_h1ah[NMAX * 256], g_h1al[NMAX * 256]; // layer1 out, bf16 split
__device__ float g_h2 [NMAX * 40];            // h1a @ W2 (fp32, for attn2)
__device__ __half g_h2f[NMAX * 40];           // fp16 for agg2 gather
__device__ float g_as1[NMAX * 4], g_ad1[NMAX * 4];
__device__ float g_as2[NMAX],     g_ad2[NMAX];
__device__ int   g_deg[NMAX], g_off[NMAX + 1], g_cur[NMAX];
__device__ int   g_csr[EMAX];
__device__ int   g_dstv[EMAX];
__device__ float g_w1[EMAX * 4];
__device__ float g_w2[EMAX];
__device__ int   g_is64;
// bf16 split operands for tensor-core GEMMs
__device__ __nv_bfloat16 g_xh[NMAX * 256], g_xl[NMAX * 256];
__device__ __nv_bfloat16 g_wh[256 * 256],  g_wl[256 * 256];
__device__ __nv_bfloat16 g_w2h[256 * 64],  g_w2l[256 * 64];   // W2 padded 40->64

// ---------------- PTX helpers ----------------
__device__ __forceinline__ unsigned smem_u32(const void* p) {
    return (unsigned)__cvta_generic_to_shared(p);
}
__device__ __forceinline__ void ldsm_x4(unsigned addr, unsigned& r0, unsigned& r1, unsigned& r2, unsigned& r3) {
    asm volatile("ldmatrix.sync.aligned.m8n8.x4.shared.b16 {%0,%1,%2,%3},[%4];"
                 : "=r"(r0), "=r"(r1), "=r"(r2), "=r"(r3) : "r"(addr));
}
__device__ __forceinline__ void ldsm_x4t(unsigned addr, unsigned& r0, unsigned& r1, unsigned& r2, unsigned& r3) {
    asm volatile("ldmatrix.sync.aligned.m8n8.x4.trans.shared.b16 {%0,%1,%2,%3},[%4];"
                 : "=r"(r0), "=r"(r1), "=r"(r2), "=r"(r3) : "r"(addr));
}
__device__ __forceinline__ void mma_bf16(float* c, unsigned a0, unsigned a1, unsigned a2, unsigned a3,
                                         unsigned b0, unsigned b1) {
    asm volatile("mma.sync.aligned.m16n8k16.row.col.f32.bf16.bf16.f32 "
                 "{%0,%1,%2,%3},{%4,%5,%6,%7},{%8,%9},{%0,%1,%2,%3};"
                 : "+f"(c[0]), "+f"(c[1]), "+f"(c[2]), "+f"(c[3])
                 : "r"(a0), "r"(a1), "r"(a2), "r"(a3), "r"(b0), "r"(b1));
}

// ---------------- bf16 split conversion ----------------
__global__ void k_split(const float* __restrict__ src, __nv_bfloat16* __restrict__ hi,
                        __nv_bfloat16* __restrict__ lo, int n) {
    int i = blockIdx.x * blockDim.x + threadIdx.x;
    if (i >= n) return;
    float v = src[i];
    __nv_bfloat16 h = __float2bfloat16(v);
    hi[i] = h;
    lo[i] = __float2bfloat16(v - __bfloat162float(h));
}

__global__ void k_split_w2(const float* __restrict__ W2) {
    int i = blockIdx.x * blockDim.x + threadIdx.x;   // over 256*64
    if (i >= 256 * 64) return;
    int r = i >> 6, c = i & 63;
    float v = (c < 40) ? W2[r * 40 + c] : 0.f;
    __nv_bfloat16 h = __float2bfloat16(v);
    g_w2h[i] = h;
    g_w2l[i] = __float2bfloat16(v - __bfloat162float(h));
}

// ---------------- edge dtype detection + zero deg (fused) ----------------
__global__ void k_detect(const int* __restrict__ e32, int E, int N) {
    int i = blockIdx.x * blockDim.x + threadIdx.x;
    if (i < N) g_deg[i] = 0;
    if (blockIdx.x == 0 && threadIdx.x < 32) {
        int lane = threadIdx.x;
        int nz = 0;
        for (int k = lane; k < 64; k += 32)
            if (k < E) nz |= (e32[2 * k + 1] != 0);
        unsigned b = __ballot_sync(0xffffffffu, nz);
        if (lane == 0) g_is64 = (b == 0u);
    }
}

__device__ __forceinline__ int edge_at(const void* edge, int is64, long long idx) {
    if (is64) return (int)((const long long*)edge)[idx];
    return ((const int*)edge)[idx];
}

// ---------------- CSR build ----------------
__global__ void k_count(const void* __restrict__ edge, int E, int N) {
    int e = blockIdx.x * blockDim.x + threadIdx.x;
    int ET = E + N;
    if (e >= ET) return;
    int is64 = g_is64;
    int dst = (e < E) ? edge_at(edge, is64, (long long)E + e) : (e - E);
    atomicAdd(&g_deg[dst], 1);
}

__global__ void __launch_bounds__(1024) k_scan_fused(int N) {
    __shared__ int s[1024];
    int t = threadIdx.x;
    int chunk = (N + 1023) >> 10;
    int base = t * chunk;
    int sum = 0;
    for (int i = 0; i < chunk; i++) {
        int idx = base + i;
        if (idx < N) sum += g_deg[idx];
    }
    s[t] = sum;
    __syncthreads();
    for (int o = 1; o < 1024; o <<= 1) {
        int v = (t >= o) ? s[t - o] : 0;
        __syncthreads();
        s[t] += v;
        __syncthreads();
    }
    int run = s[t] - sum;
    for (int i = 0; i < chunk; i++) {
        int idx = base + i;
        if (idx < N) {
            g_off[idx] = run;
            g_cur[idx] = run;
            run += g_deg[idx];
        }
    }
    if (t == 1023) g_off[N] = s[1023];
}

__global__ void k_scatter(const void* __restrict__ edge, int E, int N) {
    int e = blockIdx.x * blockDim.x + threadIdx.x;
    int ET = E + N;
    if (e >= ET) return;
    int src, dst;
    if (e < E) {
        int is64 = g_is64;
        src = edge_at(edge, is64, e);
        dst = edge_at(edge, is64, (long long)E + e);
    } else {
        src = dst = e - E;
    }
    int pos = atomicAdd(&g_cur[dst], 1);
    g_csr[pos]  = src;
    g_dstv[pos] = dst;
}

// ---------------- GEMM1 (tensor core): 128x128 tile, fused attn1, fp16-only epilogue ----------------
#define LDA 40
#define LDB1 136
__global__ void __launch_bounds__(256, 2) k_gemm1_tc(int M,
        const float* __restrict__ att_s, const float* __restrict__ att_d) {
    __shared__ __nv_bfloat16 Ah[128 * LDA], Al[128 * LDA];
    __shared__ __nv_bfloat16 Bh[32 * LDB1], Bl[32 * LDB1];
    int tid = threadIdx.x;
    int warp = tid >> 5, lane = tid & 31;
    int wm = warp & 3, wn = warp >> 2;
    int row0 = blockIdx.y * 128, col0 = blockIdx.x * 128;

    float acc[2][8][4];
#pragma unroll
    for (int mi = 0; mi < 2; mi++)
#pragma unroll
        for (int ni = 0; ni < 8; ni++)
#pragma unroll
            for (int k = 0; k < 4; k++) acc[mi][ni][k] = 0.f;

    int lrow = lane & 15, lcb = lane >> 4;

    for (int kt = 0; kt < 256; kt += 32) {
        // A tile 128x32 hi+lo
#pragma unroll
        for (int i = 0; i < 2; i++) {
            int v = tid + i * 256;
            int r = v >> 2, cv = (v & 3) * 8;
            int gr = row0 + r;
            uint4 vh, vl;
            if (gr < M) {
                vh = *(const uint4*)&g_xh[(size_t)gr * 256 + kt + cv];
                vl = *(const uint4*)&g_xl[(size_t)gr * 256 + kt + cv];
            } else { vh = make_uint4(0,0,0,0); vl = vh; }
            *(uint4*)&Ah[r * LDA + cv] = vh;
            *(uint4*)&Al[r * LDA + cv] = vl;
        }
        // B tile 32x128 hi+lo
#pragma unroll
        for (int i = 0; i < 2; i++) {
            int v = tid + i * 256;
            int r = v >> 4, cv = (v & 15) * 8;
            *(uint4*)&Bh[r * LDB1 + cv] = *(const uint4*)&g_wh[(size_t)(kt + r) * 256 + col0 + cv];
            *(uint4*)&Bl[r * LDB1 + cv] = *(const uint4*)&g_wl[(size_t)(kt + r) * 256 + col0 + cv];
        }
        __syncthreads();

#pragma unroll
        for (int ks = 0; ks < 32; ks += 16) {
            unsigned ah[2][4], al[2][4], bh[4][4], bl[4][4];
#pragma unroll
            for (int mi = 0; mi < 2; mi++) {
                unsigned ad = smem_u32(&Ah[(wm * 32 + mi * 16 + lrow) * LDA + ks + lcb * 8]);
                ldsm_x4(ad, ah[mi][0], ah[mi][1], ah[mi][2], ah[mi][3]);
                unsigned ad2 = smem_u32(&Al[(wm * 32 + mi * 16 + lrow) * LDA + ks + lcb * 8]);
                ldsm_x4(ad2, al[mi][0], al[mi][1], al[mi][2], al[mi][3]);
            }
#pragma unroll
            for (int nj = 0; nj < 4; nj++) {
                unsigned bd = smem_u32(&Bh[(ks + lrow) * LDB1 + wn * 64 + nj * 16 + lcb * 8]);
                ldsm_x4t(bd, bh[nj][0], bh[nj][1], bh[nj][2], bh[nj][3]);
                unsigned bd2 = smem_u32(&Bl[(ks + lrow) * LDB1 + wn * 64 + nj * 16 + lcb * 8]);
                ldsm_x4t(bd2, bl[nj][0], bl[nj][1], bl[nj][2], bl[nj][3]);
            }
#pragma unroll
            for (int mi = 0; mi < 2; mi++)
#pragma unroll
                for (int ni = 0; ni < 8; ni++) {
                    int nj = ni >> 1, s2 = (ni & 1) * 2;
                    mma_bf16(acc[mi][ni], ah[mi][0], ah[mi][1], ah[mi][2], ah[mi][3],
                             bh[nj][s2], bh[nj][s2 + 1]);
                    mma_bf16(acc[mi][ni], ah[mi][0], ah[mi][1], ah[mi][2], ah[mi][3],
                             bl[nj][s2], bl[nj][s2 + 1]);
                    mma_bf16(acc[mi][ni], al[mi][0], al[mi][1], al[mi][2], al[mi][3],
                             bh[nj][s2], bh[nj][s2 + 1]);
                }
        }
        __syncthreads();
    }

    // epilogue: fp16 stores + fused attn1.
    // This warp's 64 cols (col0 + wn*64 .. +63) = exactly one head.
    int tr = lane >> 2, tc = (lane & 3) * 2;
    int head = blockIdx.x * 2 + wn;
#pragma unroll
    for (int mi = 0; mi < 2; mi++) {
        float ps0 = 0.f, pd0 = 0.f, ps1 = 0.f, pd1 = 0.f;
#pragma unroll
        for (int ni = 0; ni < 8; ni++) {
            int r = row0 + wm * 32 + mi * 16 + tr;
            int c = col0 + wn * 64 + ni * 8 + tc;
            if (r < M)
                *(__half2*)&g_h1f[(size_t)r * 256 + c] = __floats2half2_rn(acc[mi][ni][0], acc[mi][ni][1]);
            if (r + 8 < M)
                *(__half2*)&g_h1f[(size_t)(r + 8) * 256 + c] = __floats2half2_rn(acc[mi][ni][2], acc[mi][ni][3]);
            float s0 = __ldg(&att_s[c]), s1 = __ldg(&att_s[c + 1]);
            float d0 = __ldg(&att_d[c]), d1 = __ldg(&att_d[c + 1]);
            ps0 = fmaf(acc[mi][ni][0], s0, ps0); ps0 = fmaf(acc[mi][ni][1], s1, ps0);
            pd0 = fmaf(acc[mi][ni][0], d0, pd0); pd0 = fmaf(acc[mi][ni][1], d1, pd0);
            ps1 = fmaf(acc[mi][ni][2], s0, ps1); ps1 = fmaf(acc[mi][ni][3], s1, ps1);
            pd1 = fmaf(acc[mi][ni][2], d0, pd1); pd1 = fmaf(acc[mi][ni][3], d1, pd1);
        }
        // reduce over the 4 lanes sharing a row (lane ids tr*4 + 0..3)
        ps0 += __shfl_xor_sync(0xffffffffu, ps0, 1); ps0 += __shfl_xor_sync(0xffffffffu, ps0, 2);
        pd0 += __shfl_xor_sync(0xffffffffu, pd0, 1); pd0 += __shfl_xor_sync(0xffffffffu, pd0, 2);
        ps1 += __shfl_xor_sync(0xffffffffu, ps1, 1); ps1 += __shfl_xor_sync(0xffffffffu, ps1, 2);
        pd1 += __shfl_xor_sync(0xffffffffu, pd1, 1); pd1 += __shfl_xor_sync(0xffffffffu, pd1, 2);
        if ((lane & 3) == 0) {
            int r0 = row0 + wm * 32 + mi * 16 + tr;
            if (r0 < M)     { g_as1[r0 * 4 + head] = ps0; g_ad1[r0 * 4 + head] = pd0; }
            if (r0 + 8 < M) { g_as1[(r0 + 8) * 4 + head] = ps1; g_ad1[(r0 + 8) * 4 + head] = pd1; }
        }
    }
}

// ---------------- GEMM2 (tensor core): h2 = h1a @ W2pad ----------------
#define LDB 72
__global__ void __launch_bounds__(256) k_gemm2_tc(int M) {
    __shared__ __nv_bfloat16 Ah[128 * LDA], Al[128 * LDA];
    __shared__ __nv_bfloat16 Bh[32 * LDB],  Bl[32 * LDB];
    int tid = threadIdx.x;
    int warp = tid >> 5, lane = tid & 31;
    int wm = warp & 3, wn = warp >> 2;
    int row0 = blockIdx.x * 128;

    float acc[2][4][4];
#pragma unroll
    for (int mi = 0; mi < 2; mi++)
#pragma unroll
        for (int ni = 0; ni < 4; ni++)
#pragma unroll
            for (int k = 0; k < 4; k++) acc[mi][ni][k] = 0.f;

    int lrow = lane & 15, lcb = lane >> 4;

    for (int kt = 0; kt < 256; kt += 32) {
#pragma unroll
        for (int i = 0; i < 2; i++) {
            int v = tid + i * 256;
            int r = v >> 2, cv = (v & 3) * 8;
            int gr = row0 + r;
            uint4 vh, vl;
            if (gr < M) {
                vh = *(const uint4*)&g_h1ah[(size_t)gr * 256 + kt + cv];
                vl = *(const uint4*)&g_h1al[(size_t)gr * 256 + kt + cv];
            } else { vh = make_uint4(0,0,0,0); vl = vh; }
            *(uint4*)&Ah[r * LDA + cv] = vh;
            *(uint4*)&Al[r * LDA + cv] = vl;
        }
        {
            int r = tid >> 3, cv = (tid & 7) * 8;
            *(uint4*)&Bh[r * LDB + cv] = *(const uint4*)&g_w2h[(size_t)(kt + r) * 64 + cv];
            *(uint4*)&Bl[r * LDB + cv] = *(const uint4*)&g_w2l[(size_t)(kt + r) * 64 + cv];
        }
        __syncthreads();

#pragma unroll
        for (int ks = 0; ks < 32; ks += 16) {
            unsigned ah[2][4], al[2][4], bh[2][4], bl[2][4];
#pragma unroll
            for (int mi = 0; mi < 2; mi++) {
                unsigned ad = smem_u32(&Ah[(wm * 32 + mi * 16 + lrow) * LDA + ks + lcb * 8]);
                ldsm_x4(ad, ah[mi][0], ah[mi][1], ah[mi][2], ah[mi][3]);
                unsigned ad2 = smem_u32(&Al[(wm * 32 + mi * 16 + lrow) * LDA + ks + lcb * 8]);
                ldsm_x4(ad2, al[mi][0], al[mi][1], al[mi][2], al[mi][3]);
            }
#pragma unroll
            for (int nj = 0; nj < 2; nj++) {
                unsigned bd = smem_u32(&Bh[(ks + lrow) * LDB + wn * 32 + nj * 16 + lcb * 8]);
                ldsm_x4t(bd, bh[nj][0], bh[nj][1], bh[nj][2], bh[nj][3]);
                unsigned bd2 = smem_u32(&Bl[(ks + lrow) * LDB + wn * 32 + nj * 16 + lcb * 8]);
                ldsm_x4t(bd2, bl[nj][0], bl[nj][1], bl[nj][2], bl[nj][3]);
            }
#pragma unroll
            for (int mi = 0; mi < 2; mi++)
#pragma unroll
                for (int ni = 0; ni < 4; ni++) {
                    int nj = ni >> 1, s2 = (ni & 1) * 2;
                    mma_bf16(acc[mi][ni], ah[mi][0], ah[mi][1], ah[mi][2], ah[mi][3],
                             bh[nj][s2], bh[nj][s2 + 1]);
                    mma_bf16(acc[mi][ni], ah[mi][0], ah[mi][1], ah[mi][2], ah[mi][3],
                             bl[nj][s2], bl[nj][s2 + 1]);
                    mma_bf16(acc[mi][ni], al[mi][0], al[mi][1], al[mi][2], al[mi][3],
                             bh[nj][s2], bh[nj][s2 + 1]);
                }
        }
        __syncthreads();
    }

    int tr = lane >> 2, tc = (lane & 3) * 2;
#pragma unroll
    for (int mi = 0; mi < 2; mi++)
#pragma unroll
        for (int ni = 0; ni < 4; ni++) {
            int r = row0 + wm * 32 + mi * 16 + tr;
            int c = wn * 32 + ni * 8 + tc;
            if (c < 40) {
                if (r < M) {
                    g_h2[(size_t)r * 40 + c]     = acc[mi][ni][0];
                    g_h2[(size_t)r * 40 + c + 1] = acc[mi][ni][1];
                    *(__half2*)&g_h2f[(size_t)r * 40 + c] = __floats2half2_rn(acc[mi][ni][0], acc[mi][ni][1]);
                }
                if (r + 8 < M) {
                    g_h2[(size_t)(r + 8) * 40 + c]     = acc[mi][ni][2];
                    g_h2[(size_t)(r + 8) * 40 + c + 1] = acc[mi][ni][3];
                    *(__half2*)&g_h2f[(size_t)(r + 8) * 40 + c] = __floats2half2_rn(acc[mi][ni][2], acc[mi][ni][3]);
                }
            }
        }
}

// ---------------- edge weights layer1 ----------------
__global__ void k_edgew1(int ET) {
    int e = blockIdx.x * blockDim.x + threadIdx.x;
    if (e >= ET) return;
    int s = g_csr[e], d = g_dstv[e];
    float4 as = *(const float4*)&g_as1[s * 4];
    float4 ad = *(const float4*)&g_ad1[d * 4];
    float e0 = as.x + ad.x; e0 = e0 > 0.f ? e0 : 0.2f * e0;
    float e1 = as.y + ad.y; e1 = e1 > 0.f ? e1 : 0.2f * e1;
    float e2 = as.z + ad.z; e2 = e2 > 0.f ? e2 : 0.2f * e2;
    float e3 = as.w + ad.w; e3 = e3 > 0.f ? e3 : 0.2f * e3;
    float4 w = make_float4(__expf(e0), __expf(e1), __expf(e2), __expf(e3));
    *(float4*)&g_w1[e * 4] = w;
}

// ---------------- agg1: fp16 gather, weighted sum / denom, + bias + ELU, bf16-split out ----------------
__global__ void k_agg1(const float* __restrict__ bias, int M) {
    int w = (blockIdx.x * blockDim.x + threadIdx.x) >> 5;
    int lane = threadIdx.x & 31;
    if (w >= M) return;
    int start = g_off[w], end = g_off[w + 1];
    int hh = lane >> 3;
    int c0 = lane * 8;

    float acc[8] = {0.f, 0.f, 0.f, 0.f, 0.f, 0.f, 0.f, 0.f};
    float denom = 0.f;
    int j = start;
    for (; j + 1 < end; j += 2) {
        int s0 = g_csr[j], s1 = g_csr[j + 1];
        float w0 = g_w1[j * 4 + hh], w1 = g_w1[(j + 1) * 4 + hh];
        uint4 q0 = *(const uint4*)&g_h1f[(size_t)s0 * 256 + c0];
        uint4 q1 = *(const uint4*)&g_h1f[(size_t)s1 * 256 + c0];
        denom += w0 + w1;
        const __half2* a = (const __half2*)&q0;
        const __half2* b = (const __half2*)&q1;
#pragma unroll
        for (int k = 0; k < 4; k++) {
            float2 fa = __half22float2(a[k]);
            float2 fb = __half22float2(b[k]);
            acc[2*k]   = fmaf(w0, fa.x, acc[2*k]);   acc[2*k]   = fmaf(w1, fb.x, acc[2*k]);
            acc[2*k+1] = fmaf(w0, fa.y, acc[2*k+1]); acc[2*k+1] = fmaf(w1, fb.y, acc[2*k+1]);
        }
    }
    if (j < end) {
        int s0 = g_csr[j];
        float w0 = g_w1[j * 4 + hh];
        uint4 q0 = *(const uint4*)&g_h1f[(size_t)s0 * 256 + c0];
        denom += w0;
        const __half2* a = (const __half2*)&q0;
#pragma unroll
        for (int k = 0; k < 4; k++) {
            float2 fa = __half22float2(a[k]);
            acc[2*k]   = fmaf(w0, fa.x, acc[2*k]);
            acc[2*k+1] = fmaf(w0, fa.y, acc[2*k+1]);
        }
    }
    float inv = 1.f / denom;
    __nv_bfloat16 hi8[8], lo8[8];
#pragma unroll
    for (int k = 0; k < 8; k++) {
        float v = acc[k] * inv + bias[c0 + k];
        v = v > 0.f ? v : (__expf(v) - 1.f);   // ELU
        __nv_bfloat16 h = __float2bfloat16(v);
        hi8[k] = h;
        lo8[k] = __float2bfloat16(v - __bfloat162float(h));
    }
    *(uint4*)&g_h1ah[(size_t)w * 256 + c0] = *(const uint4*)hi8;
    *(uint4*)&g_h1al[(size_t)w * 256 + c0] = *(const uint4*)lo8;
}

// ---------------- attn2 ----------------
__global__ void k_attn2(const float* __restrict__ att_s, const float* __restrict__ att_d, int M) {
    int w = (blockIdx.x * blockDim.x + threadIdx.x) >> 5;
    int lane = threadIdx.x & 31;
    if (w >= M) return;
    const float* h = &g_h2[(size_t)w * 40];
    float ps = h[lane] * __ldg(&att_s[lane]);
    float pd = h[lane] * __ldg(&att_d[lane]);
    if (lane < 8) {
        ps += h[32 + lane] * __ldg(&att_s[32 + lane]);
        pd += h[32 + lane] * __ldg(&att_d[32 + lane]);
    }
#pragma unroll
    for (int o = 16; o >= 1; o >>= 1) {
        ps += __shfl_xor_sync(0xffffffffu, ps, o);
        pd += __shfl_xor_sync(0xffffffffu, pd, o);
    }
    if (lane == 0) { g_as2[w] = ps; g_ad2[w] = pd; }
}

// ---------------- edge weights layer2 ----------------
__global__ void k_edgew2(int ET) {
    int e = blockIdx.x * blockDim.x + threadIdx.x;
    if (e >= ET) return;
    int s = g_csr[e], d = g_dstv[e];
    float ev = g_as2[s] + g_ad2[d];
    ev = ev > 0.f ? ev : 0.2f * ev;
    g_w2[e] = __expf(ev);
}

// ---------------- agg2: fp16 gather, final output ----------------
__global__ void k_agg2(const float* __restrict__ b2, float* __restrict__ out, int M) {
    int w = (blockIdx.x * blockDim.x + threadIdx.x) >> 5;
    int lane = threadIdx.x & 31;
    if (w >= M) return;
    int start = g_off[w], end = g_off[w + 1];
    bool val = lane < 20;
    float denom = 0.f, acc0 = 0.f, acc1 = 0.f;
    int j = start;
    for (; j + 1 < end; j += 2) {
        int s0 = g_csr[j], s1 = g_csr[j + 1];
        float w0 = g_w2[j], w1 = g_w2[j + 1];
        float2 f0 = make_float2(0.f, 0.f), f1 = f0;
        if (val) {
            f0 = __half22float2(*(const __half2*)&g_h2f[(size_t)s0 * 40 + lane * 2]);
            f1 = __half22float2(*(const __half2*)&g_h2f[(size_t)s1 * 40 + lane * 2]);
        }
        denom += w0 + w1;
        acc0 = fmaf(w0, f0.x, acc0); acc0 = fmaf(w1, f1.x, acc0);
        acc1 = fmaf(w0, f0.y, acc1); acc1 = fmaf(w1, f1.y, acc1);
    }
    if (j < end) {
        int s0 = g_csr[j];
        float w0 = g_w2[j];
        float2 f0 = make_float2(0.f, 0.f);
        if (val) f0 = __half22float2(*(const __half2*)&g_h2f[(size_t)s0 * 40 + lane * 2]);
        denom += w0;
        acc0 = fmaf(w0, f0.x, acc0);
        acc1 = fmaf(w0, f0.y, acc1);
    }
    float inv = 1.f / denom;
    if (val) {
        out[(size_t)w * 40 + lane * 2]     = acc0 * inv + __ldg(&b2[lane * 2]);
        out[(size_t)w * 40 + lane * 2 + 1] = acc1 * inv + __ldg(&b2[lane * 2 + 1]);
    }
}

// ---------------- launch ----------------
extern "C" void kernel_launch(void* const* d_in, const int* in_sizes, int n_in,
                              void* d_out, int out_size) {
    const float* x    = (const float*)d_in[0];
    const void*  edge = (const void*)d_in[1];
    const float* W1   = (const float*)d_in[2];
    const float* as1  = (const float*)d_in[3];
    const float* ad1  = (const float*)d_in[4];
    const float* b1   = (const float*)d_in[5];
    const float* W2   = (const float*)d_in[6];
    const float* as2  = (const float*)d_in[7];
    const float* ad2  = (const float*)d_in[8];
    const float* b2   = (const float*)d_in[9];
    float* out = (float*)d_out;

    int N  = in_sizes[0] / 256;
    int E  = in_sizes[1] / 2;
    int ET = E + N;

    __nv_bfloat16 *xh, *xl, *wh, *wl;
    cudaGetSymbolAddress((void**)&xh, g_xh);
    cudaGetSymbolAddress((void**)&xl, g_xl);
    cudaGetSymbolAddress((void**)&wh, g_wh);
    cudaGetSymbolAddress((void**)&wl, g_wl);
    int nx = N * 256;

    // launch idx: 0,1 splits; 2 detect+zero; 3 gemm1_tc (profiled slot)
    k_split<<<(nx + 255) / 256, 256>>>(x, xh, xl, nx);
    k_split<<<(65536 + 255) / 256, 256>>>(W1, wh, wl, 65536);
    k_detect<<<(N + 255) / 256, 256>>>((const int*)edge, E, N);
    k_gemm1_tc<<<dim3(2, (N + 127) / 128), 256>>>(N, as1, ad1);

    k_split_w2<<<(256 * 64 + 255) / 256, 256>>>(W2);

    // CSR build
    k_count<<<(ET + 255) / 256, 256>>>(edge, E, N);
    k_scan_fused<<<1, 1024>>>(N);
    k_scatter<<<(ET + 255) / 256, 256>>>(edge, E, N);

    // Layer 1
    int warpGrid = (N * 32 + 255) / 256;
    k_edgew1<<<(ET + 255) / 256, 256>>>(ET);
    k_agg1<<<warpGrid, 256>>>(b1, N);

    // Layer 2
    k_gemm2_tc<<<(N + 127) / 128, 256>>>(N);
    k_attn2<<<warpGrid, 256>>>(as2, ad2, N);
    k_edgew2<<<(ET + 255) / 256, 256>>>(ET);
    k_agg2<<<warpGrid, 256>>>(b2, out, N);
}

// round 11
// speedup vs baseline: 1.6469x; 1.1298x over previous
#include <cuda_runtime.h>
#include <cuda_bf16.h>
#include <cuda_fp16.h>
#include <cstdint>
#include <math.h>

// ---------------- static scratch (no allocs allowed) ----------------
#define NMAX 50176
#define EMAX 1700000

__device__ __half g_h1f[NMAX * 256];          // x @ W1 (fp16, for agg1 gather)
__device__ __nv_bfloat16 g_h1ah[NMAX * 256], g_h1al[NMAX * 256]; // layer1 out, bf16 split
__device__ float g_h2 [NMAX * 40];            // h1a @ W2 (fp32, for attn2)
__device__ __half g_h2f[NMAX * 40];           // fp16 for agg2 gather
__device__ float g_as1[NMAX * 4], g_ad1[NMAX * 4];
__device__ float g_as2[NMAX],     g_ad2[NMAX];
__device__ int   g_deg[NMAX], g_off[NMAX + 1], g_cur[NMAX];
__device__ int   g_csr[EMAX];
__device__ int   g_is64;
// bf16 split operands for tensor-core GEMMs
__device__ __nv_bfloat16 g_wh[256 * 256],  g_wl[256 * 256];
__device__ __nv_bfloat16 g_w2h[256 * 64],  g_w2l[256 * 64];   // W2 padded 40->64

// ---------------- PTX helpers ----------------
__device__ __forceinline__ unsigned smem_u32(const void* p) {
    return (unsigned)__cvta_generic_to_shared(p);
}
__device__ __forceinline__ void ldsm_x4(unsigned addr, unsigned& r0, unsigned& r1, unsigned& r2, unsigned& r3) {
    asm volatile("ldmatrix.sync.aligned.m8n8.x4.shared.b16 {%0,%1,%2,%3},[%4];"
                 : "=r"(r0), "=r"(r1), "=r"(r2), "=r"(r3) : "r"(addr));
}
__device__ __forceinline__ void ldsm_x4t(unsigned addr, unsigned& r0, unsigned& r1, unsigned& r2, unsigned& r3) {
    asm volatile("ldmatrix.sync.aligned.m8n8.x4.trans.shared.b16 {%0,%1,%2,%3},[%4];"
                 : "=r"(r0), "=r"(r1), "=r"(r2), "=r"(r3) : "r"(addr));
}
__device__ __forceinline__ void mma_bf16(float* c, unsigned a0, unsigned a1, unsigned a2, unsigned a3,
                                         unsigned b0, unsigned b1) {
    asm volatile("mma.sync.aligned.m16n8k16.row.col.f32.bf16.bf16.f32 "
                 "{%0,%1,%2,%3},{%4,%5,%6,%7},{%8,%9},{%0,%1,%2,%3};"
                 : "+f"(c[0]), "+f"(c[1]), "+f"(c[2]), "+f"(c[3])
                 : "r"(a0), "r"(a1), "r"(a2), "r"(a3), "r"(b0), "r"(b1));
}

// ---------------- bf16 split conversion (W1 only) ----------------
__global__ void k_split(const float* __restrict__ src, __nv_bfloat16* __restrict__ hi,
                        __nv_bfloat16* __restrict__ lo, int n) {
    int i = blockIdx.x * blockDim.x + threadIdx.x;
    if (i >= n) return;
    float v = src[i];
    __nv_bfloat16 h = __float2bfloat16(v);
    hi[i] = h;
    lo[i] = __float2bfloat16(v - __bfloat162float(h));
}

__global__ void k_split_w2(const float* __restrict__ W2) {
    int i = blockIdx.x * blockDim.x + threadIdx.x;   // over 256*64
    if (i >= 256 * 64) return;
    int r = i >> 6, c = i & 63;
    float v = (c < 40) ? W2[r * 40 + c] : 0.f;
    __nv_bfloat16 h = __float2bfloat16(v);
    g_w2h[i] = h;
    g_w2l[i] = __float2bfloat16(v - __bfloat162float(h));
}

// ---------------- edge dtype detection + zero deg (fused) ----------------
__global__ void k_detect(const int* __restrict__ e32, int E, int N) {
    int i = blockIdx.x * blockDim.x + threadIdx.x;
    if (i < N) g_deg[i] = 0;
    if (blockIdx.x == 0 && threadIdx.x < 32) {
        int lane = threadIdx.x;
        int nz = 0;
        for (int k = lane; k < 64; k += 32)
            if (k < E) nz |= (e32[2 * k + 1] != 0);
        unsigned b = __ballot_sync(0xffffffffu, nz);
        if (lane == 0) g_is64 = (b == 0u);
    }
}

__device__ __forceinline__ int edge_at(const void* edge, int is64, long long idx) {
    if (is64) return (int)((const long long*)edge)[idx];
    return ((const int*)edge)[idx];
}

// ---------------- CSR build ----------------
__global__ void k_count(const void* __restrict__ edge, int E, int N) {
    int e = blockIdx.x * blockDim.x + threadIdx.x;
    int ET = E + N;
    if (e >= ET) return;
    int is64 = g_is64;
    int dst = (e < E) ? edge_at(edge, is64, (long long)E + e) : (e - E);
    atomicAdd(&g_deg[dst], 1);
}

__global__ void __launch_bounds__(1024) k_scan_fused(int N) {
    __shared__ int s[1024];
    int t = threadIdx.x;
    int chunk = (N + 1023) >> 10;
    int base = t * chunk;
    int sum = 0;
    for (int i = 0; i < chunk; i++) {
        int idx = base + i;
        if (idx < N) sum += g_deg[idx];
    }
    s[t] = sum;
    __syncthreads();
    for (int o = 1; o < 1024; o <<= 1) {
        int v = (t >= o) ? s[t - o] : 0;
        __syncthreads();
        s[t] += v;
        __syncthreads();
    }
    int run = s[t] - sum;
    for (int i = 0; i < chunk; i++) {
        int idx = base + i;
        if (idx < N) {
            g_off[idx] = run;
            g_cur[idx] = run;
            run += g_deg[idx];
        }
    }
    if (t == 1023) g_off[N] = s[1023];
}

__global__ void k_scatter(const void* __restrict__ edge, int E, int N) {
    int e = blockIdx.x * blockDim.x + threadIdx.x;
    int ET = E + N;
    if (e >= ET) return;
    int src, dst;
    if (e < E) {
        int is64 = g_is64;
        src = edge_at(edge, is64, e);
        dst = edge_at(edge, is64, (long long)E + e);
    } else {
        src = dst = e - E;
    }
    int pos = atomicAdd(&g_cur[dst], 1);
    g_csr[pos] = src;
}

// ---------------- GEMM1: x fp32 loaded directly, split in-kernel; fused attn1 ----------------
#define LDA 40
#define LDB1 136
__global__ void __launch_bounds__(256, 2) k_gemm1_tc(const float* __restrict__ X, int M,
        const float* __restrict__ att_s, const float* __restrict__ att_d) {
    __shared__ __nv_bfloat16 Ah[128 * LDA], Al[128 * LDA];
    __shared__ __nv_bfloat16 Bh[32 * LDB1], Bl[32 * LDB1];
    int tid = threadIdx.x;
    int warp = tid >> 5, lane = tid & 31;
    int wm = warp & 3, wn = warp >> 2;
    int row0 = blockIdx.y * 128, col0 = blockIdx.x * 128;

    float acc[2][8][4];
#pragma unroll
    for (int mi = 0; mi < 2; mi++)
#pragma unroll
        for (int ni = 0; ni < 8; ni++)
#pragma unroll
            for (int k = 0; k < 4; k++) acc[mi][ni][k] = 0.f;

    int lrow = lane & 15, lcb = lane >> 4;

    for (int kt = 0; kt < 256; kt += 32) {
        // A tile 128x32: load fp32, split to bf16 hi/lo in-register
#pragma unroll
        for (int i = 0; i < 2; i++) {
            int v = tid + i * 256;
            int r = v >> 2, cv = (v & 3) * 8;
            int gr = row0 + r;
            float4 f0 = make_float4(0.f, 0.f, 0.f, 0.f), f1 = f0;
            if (gr < M) {
                f0 = *(const float4*)&X[(size_t)gr * 256 + kt + cv];
                f1 = *(const float4*)&X[(size_t)gr * 256 + kt + cv + 4];
            }
            float fv[8] = {f0.x, f0.y, f0.z, f0.w, f1.x, f1.y, f1.z, f1.w};
            __nv_bfloat16 hb[8], lb[8];
#pragma unroll
            for (int k = 0; k < 8; k++) {
                hb[k] = __float2bfloat16(fv[k]);
                lb[k] = __float2bfloat16(fv[k] - __bfloat162float(hb[k]));
            }
            *(uint4*)&Ah[r * LDA + cv] = *(const uint4*)hb;
            *(uint4*)&Al[r * LDA + cv] = *(const uint4*)lb;
        }
        // B tile 32x128 hi+lo
#pragma unroll
        for (int i = 0; i < 2; i++) {
            int v = tid + i * 256;
            int r = v >> 4, cv = (v & 15) * 8;
            *(uint4*)&Bh[r * LDB1 + cv] = *(const uint4*)&g_wh[(size_t)(kt + r) * 256 + col0 + cv];
            *(uint4*)&Bl[r * LDB1 + cv] = *(const uint4*)&g_wl[(size_t)(kt + r) * 256 + col0 + cv];
        }
        __syncthreads();

#pragma unroll
        for (int ks = 0; ks < 32; ks += 16) {
            unsigned ah[2][4], al[2][4], bh[4][4], bl[4][4];
#pragma unroll
            for (int mi = 0; mi < 2; mi++) {
                unsigned ad = smem_u32(&Ah[(wm * 32 + mi * 16 + lrow) * LDA + ks + lcb * 8]);
                ldsm_x4(ad, ah[mi][0], ah[mi][1], ah[mi][2], ah[mi][3]);
                unsigned ad2 = smem_u32(&Al[(wm * 32 + mi * 16 + lrow) * LDA + ks + lcb * 8]);
                ldsm_x4(ad2, al[mi][0], al[mi][1], al[mi][2], al[mi][3]);
            }
#pragma unroll
            for (int nj = 0; nj < 4; nj++) {
                unsigned bd = smem_u32(&Bh[(ks + lrow) * LDB1 + wn * 64 + nj * 16 + lcb * 8]);
                ldsm_x4t(bd, bh[nj][0], bh[nj][1], bh[nj][2], bh[nj][3]);
                unsigned bd2 = smem_u32(&Bl[(ks + lrow) * LDB1 + wn * 64 + nj * 16 + lcb * 8]);
                ldsm_x4t(bd2, bl[nj][0], bl[nj][1], bl[nj][2], bl[nj][3]);
            }
#pragma unroll
            for (int mi = 0; mi < 2; mi++)
#pragma unroll
                for (int ni = 0; ni < 8; ni++) {
                    int nj = ni >> 1, s2 = (ni & 1) * 2;
                    mma_bf16(acc[mi][ni], ah[mi][0], ah[mi][1], ah[mi][2], ah[mi][3],
                             bh[nj][s2], bh[nj][s2 + 1]);
                    mma_bf16(acc[mi][ni], ah[mi][0], ah[mi][1], ah[mi][2], ah[mi][3],
                             bl[nj][s2], bl[nj][s2 + 1]);
                    mma_bf16(acc[mi][ni], al[mi][0], al[mi][1], al[mi][2], al[mi][3],
                             bh[nj][s2], bh[nj][s2 + 1]);
                }
        }
        __syncthreads();
    }

    // epilogue: fp16 stores + fused attn1 (warp column = one head)
    int tr = lane >> 2, tc = (lane & 3) * 2;
    int head = blockIdx.x * 2 + wn;
#pragma unroll
    for (int mi = 0; mi < 2; mi++) {
        float ps0 = 0.f, pd0 = 0.f, ps1 = 0.f, pd1 = 0.f;
#pragma unroll
        for (int ni = 0; ni < 8; ni++) {
            int r = row0 + wm * 32 + mi * 16 + tr;
            int c = col0 + wn * 64 + ni * 8 + tc;
            if (r < M)
                *(__half2*)&g_h1f[(size_t)r * 256 + c] = __floats2half2_rn(acc[mi][ni][0], acc[mi][ni][1]);
            if (r + 8 < M)
                *(__half2*)&g_h1f[(size_t)(r + 8) * 256 + c] = __floats2half2_rn(acc[mi][ni][2], acc[mi][ni][3]);
            float s0 = __ldg(&att_s[c]), s1 = __ldg(&att_s[c + 1]);
            float d0 = __ldg(&att_d[c]), d1 = __ldg(&att_d[c + 1]);
            ps0 = fmaf(acc[mi][ni][0], s0, ps0); ps0 = fmaf(acc[mi][ni][1], s1, ps0);
            pd0 = fmaf(acc[mi][ni][0], d0, pd0); pd0 = fmaf(acc[mi][ni][1], d1, pd0);
            ps1 = fmaf(acc[mi][ni][2], s0, ps1); ps1 = fmaf(acc[mi][ni][3], s1, ps1);
            pd1 = fmaf(acc[mi][ni][2], d0, pd1); pd1 = fmaf(acc[mi][ni][3], d1, pd1);
        }
        ps0 += __shfl_xor_sync(0xffffffffu, ps0, 1); ps0 += __shfl_xor_sync(0xffffffffu, ps0, 2);
        pd0 += __shfl_xor_sync(0xffffffffu, pd0, 1); pd0 += __shfl_xor_sync(0xffffffffu, pd0, 2);
        ps1 += __shfl_xor_sync(0xffffffffu, ps1, 1); ps1 += __shfl_xor_sync(0xffffffffu, ps1, 2);
        pd1 += __shfl_xor_sync(0xffffffffu, pd1, 1); pd1 += __shfl_xor_sync(0xffffffffu, pd1, 2);
        if ((lane & 3) == 0) {
            int r0 = row0 + wm * 32 + mi * 16 + tr;
            if (r0 < M)     { g_as1[r0 * 4 + head] = ps0; g_ad1[r0 * 4 + head] = pd0; }
            if (r0 + 8 < M) { g_as1[(r0 + 8) * 4 + head] = ps1; g_ad1[(r0 + 8) * 4 + head] = pd1; }
        }
    }
}

// ---------------- GEMM2 (tensor core): h2 = h1a @ W2pad ----------------
#define LDB 72
__global__ void __launch_bounds__(256) k_gemm2_tc(int M) {
    __shared__ __nv_bfloat16 Ah[128 * LDA], Al[128 * LDA];
    __shared__ __nv_bfloat16 Bh[32 * LDB],  Bl[32 * LDB];
    int tid = threadIdx.x;
    int warp = tid >> 5, lane = tid & 31;
    int wm = warp & 3, wn = warp >> 2;
    int row0 = blockIdx.x * 128;

    float acc[2][4][4];
#pragma unroll
    for (int mi = 0; mi < 2; mi++)
#pragma unroll
        for (int ni = 0; ni < 4; ni++)
#pragma unroll
            for (int k = 0; k < 4; k++) acc[mi][ni][k] = 0.f;

    int lrow = lane & 15, lcb = lane >> 4;

    for (int kt = 0; kt < 256; kt += 32) {
#pragma unroll
        for (int i = 0; i < 2; i++) {
            int v = tid + i * 256;
            int r = v >> 2, cv = (v & 3) * 8;
            int gr = row0 + r;
            uint4 vh, vl;
            if (gr < M) {
                vh = *(const uint4*)&g_h1ah[(size_t)gr * 256 + kt + cv];
                vl = *(const uint4*)&g_h1al[(size_t)gr * 256 + kt + cv];
            } else { vh = make_uint4(0,0,0,0); vl = vh; }
            *(uint4*)&Ah[r * LDA + cv] = vh;
            *(uint4*)&Al[r * LDA + cv] = vl;
        }
        {
            int r = tid >> 3, cv = (tid & 7) * 8;
            *(uint4*)&Bh[r * LDB + cv] = *(const uint4*)&g_w2h[(size_t)(kt + r) * 64 + cv];
            *(uint4*)&Bl[r * LDB + cv] = *(const uint4*)&g_w2l[(size_t)(kt + r) * 64 + cv];
        }
        __syncthreads();

#pragma unroll
        for (int ks = 0; ks < 32; ks += 16) {
            unsigned ah[2][4], al[2][4], bh[2][4], bl[2][4];
#pragma unroll
            for (int mi = 0; mi < 2; mi++) {
                unsigned ad = smem_u32(&Ah[(wm * 32 + mi * 16 + lrow) * LDA + ks + lcb * 8]);
                ldsm_x4(ad, ah[mi][0], ah[mi][1], ah[mi][2], ah[mi][3]);
                unsigned ad2 = smem_u32(&Al[(wm * 32 + mi * 16 + lrow) * LDA + ks + lcb * 8]);
                ldsm_x4(ad2, al[mi][0], al[mi][1], al[mi][2], al[mi][3]);
            }
#pragma unroll
            for (int nj = 0; nj < 2; nj++) {
                unsigned bd = smem_u32(&Bh[(ks + lrow) * LDB + wn * 32 + nj * 16 + lcb * 8]);
                ldsm_x4t(bd, bh[nj][0], bh[nj][1], bh[nj][2], bh[nj][3]);
                unsigned bd2 = smem_u32(&Bl[(ks + lrow) * LDB + wn * 32 + nj * 16 + lcb * 8]);
                ldsm_x4t(bd2, bl[nj][0], bl[nj][1], bl[nj][2], bl[nj][3]);
            }
#pragma unroll
            for (int mi = 0; mi < 2; mi++)
#pragma unroll
                for (int ni = 0; ni < 4; ni++) {
                    int nj = ni >> 1, s2 = (ni & 1) * 2;
                    mma_bf16(acc[mi][ni], ah[mi][0], ah[mi][1], ah[mi][2], ah[mi][3],
                             bh[nj][s2], bh[nj][s2 + 1]);
                    mma_bf16(acc[mi][ni], ah[mi][0], ah[mi][1], ah[mi][2], ah[mi][3],
                             bl[nj][s2], bl[nj][s2 + 1]);
                    mma_bf16(acc[mi][ni], al[mi][0], al[mi][1], al[mi][2], al[mi][3],
                             bh[nj][s2], bh[nj][s2 + 1]);
                }
        }
        __syncthreads();
    }

    int tr = lane >> 2, tc = (lane & 3) * 2;
#pragma unroll
    for (int mi = 0; mi < 2; mi++)
#pragma unroll
        for (int ni = 0; ni < 4; ni++) {
            int r = row0 + wm * 32 + mi * 16 + tr;
            int c = wn * 32 + ni * 8 + tc;
            if (c < 40) {
                if (r < M) {
                    g_h2[(size_t)r * 40 + c]     = acc[mi][ni][0];
                    g_h2[(size_t)r * 40 + c + 1] = acc[mi][ni][1];
                    *(__half2*)&g_h2f[(size_t)r * 40 + c] = __floats2half2_rn(acc[mi][ni][0], acc[mi][ni][1]);
                }
                if (r + 8 < M) {
                    g_h2[(size_t)(r + 8) * 40 + c]     = acc[mi][ni][2];
                    g_h2[(size_t)(r + 8) * 40 + c + 1] = acc[mi][ni][3];
                    *(__half2*)&g_h2f[(size_t)(r + 8) * 40 + c] = __floats2half2_rn(acc[mi][ni][2], acc[mi][ni][3]);
                }
            }
        }
}

// ---------------- agg1: inline edge weights, fp16 gather, + bias + ELU, bf16-split out ----------------
__global__ void k_agg1(const float* __restrict__ bias, int M) {
    int w = (blockIdx.x * blockDim.x + threadIdx.x) >> 5;
    int lane = threadIdx.x & 31;
    if (w >= M) return;
    int start = g_off[w], end = g_off[w + 1];
    int hh = lane >> 3;
    int c0 = lane * 8;
    float4 adv = *(const float4*)&g_ad1[w * 4];
    float adh = (hh == 0) ? adv.x : (hh == 1) ? adv.y : (hh == 2) ? adv.z : adv.w;

    float acc[8] = {0.f, 0.f, 0.f, 0.f, 0.f, 0.f, 0.f, 0.f};
    float denom = 0.f;
    int j = start;
    for (; j + 1 < end; j += 2) {
        int s0 = g_csr[j], s1 = g_csr[j + 1];
        float e0 = g_as1[s0 * 4 + hh] + adh;
        float e1 = g_as1[s1 * 4 + hh] + adh;
        e0 = e0 > 0.f ? e0 : 0.2f * e0;
        e1 = e1 > 0.f ? e1 : 0.2f * e1;
        float w0 = __expf(e0), w1 = __expf(e1);
        uint4 q0 = *(const uint4*)&g_h1f[(size_t)s0 * 256 + c0];
        uint4 q1 = *(const uint4*)&g_h1f[(size_t)s1 * 256 + c0];
        denom += w0 + w1;
        const __half2* a = (const __half2*)&q0;
        const __half2* b = (const __half2*)&q1;
#pragma unroll
        for (int k = 0; k < 4; k++) {
            float2 fa = __half22float2(a[k]);
            float2 fb = __half22float2(b[k]);
            acc[2*k]   = fmaf(w0, fa.x, acc[2*k]);   acc[2*k]   = fmaf(w1, fb.x, acc[2*k]);
            acc[2*k+1] = fmaf(w0, fa.y, acc[2*k+1]); acc[2*k+1] = fmaf(w1, fb.y, acc[2*k+1]);
        }
    }
    if (j < end) {
        int s0 = g_csr[j];
        float e0 = g_as1[s0 * 4 + hh] + adh;
        e0 = e0 > 0.f ? e0 : 0.2f * e0;
        float w0 = __expf(e0);
        uint4 q0 = *(const uint4*)&g_h1f[(size_t)s0 * 256 + c0];
        denom += w0;
        const __half2* a = (const __half2*)&q0;
#pragma unroll
        for (int k = 0; k < 4; k++) {
            float2 fa = __half22float2(a[k]);
            acc[2*k]   = fmaf(w0, fa.x, acc[2*k]);
            acc[2*k+1] = fmaf(w0, fa.y, acc[2*k+1]);
        }
    }
    float inv = 1.f / denom;
    __nv_bfloat16 hi8[8], lo8[8];
#pragma unroll
    for (int k = 0; k < 8; k++) {
        float v = acc[k] * inv + bias[c0 + k];
        v = v > 0.f ? v : (__expf(v) - 1.f);   // ELU
        __nv_bfloat16 h = __float2bfloat16(v);
        hi8[k] = h;
        lo8[k] = __float2bfloat16(v - __bfloat162float(h));
    }
    *(uint4*)&g_h1ah[(size_t)w * 256 + c0] = *(const uint4*)hi8;
    *(uint4*)&g_h1al[(size_t)w * 256 + c0] = *(const uint4*)lo8;
}

// ---------------- attn2 ----------------
__global__ void k_attn2(const float* __restrict__ att_s, const float* __restrict__ att_d, int M) {
    int w = (blockIdx.x * blockDim.x + threadIdx.x) >> 5;
    int lane = threadIdx.x & 31;
    if (w >= M) return;
    const float* h = &g_h2[(size_t)w * 40];
    float ps = h[lane] * __ldg(&att_s[lane]);
    float pd = h[lane] * __ldg(&att_d[lane]);
    if (lane < 8) {
        ps += h[32 + lane] * __ldg(&att_s[32 + lane]);
        pd += h[32 + lane] * __ldg(&att_d[32 + lane]);
    }
#pragma unroll
    for (int o = 16; o >= 1; o >>= 1) {
        ps += __shfl_xor_sync(0xffffffffu, ps, o);
        pd += __shfl_xor_sync(0xffffffffu, pd, o);
    }
    if (lane == 0) { g_as2[w] = ps; g_ad2[w] = pd; }
}

// ---------------- agg2: inline edge weights, fp16 gather, final output ----------------
__global__ void k_agg2(const float* __restrict__ b2, float* __restrict__ out, int M) {
    int w = (blockIdx.x * blockDim.x + threadIdx.x) >> 5;
    int lane = threadIdx.x & 31;
    if (w >= M) return;
    int start = g_off[w], end = g_off[w + 1];
    float adv = g_ad2[w];
    bool val = lane < 20;
    float denom = 0.f, acc0 = 0.f, acc1 = 0.f;
    int j = start;
    for (; j + 1 < end; j += 2) {
        int s0 = g_csr[j], s1 = g_csr[j + 1];
        float e0 = g_as2[s0] + adv;
        float e1 = g_as2[s1] + adv;
        e0 = e0 > 0.f ? e0 : 0.2f * e0;
        e1 = e1 > 0.f ? e1 : 0.2f * e1;
        float w0 = __expf(e0), w1 = __expf(e1);
        float2 f0 = make_float2(0.f, 0.f), f1 = f0;
        if (val) {
            f0 = __half22float2(*(const __half2*)&g_h2f[(size_t)s0 * 40 + lane * 2]);
            f1 = __half22float2(*(const __half2*)&g_h2f[(size_t)s1 * 40 + lane * 2]);
        }
        denom += w0 + w1;
        acc0 = fmaf(w0, f0.x, acc0); acc0 = fmaf(w1, f1.x, acc0);
        acc1 = fmaf(w0, f0.y, acc1); acc1 = fmaf(w1, f1.y, acc1);
    }
    if (j < end) {
        int s0 = g_csr[j];
        float e0 = g_as2[s0] + adv;
        e0 = e0 > 0.f ? e0 : 0.2f * e0;
        float w0 = __expf(e0);
        float2 f0 = make_float2(0.f, 0.f);
        if (val) f0 = __half22float2(*(const __half2*)&g_h2f[(size_t)s0 * 40 + lane * 2]);
        denom += w0;
        acc0 = fmaf(w0, f0.x, acc0);
        acc1 = fmaf(w0, f0.y, acc1);
    }
    float inv = 1.f / denom;
    if (val) {
        out[(size_t)w * 40 + lane * 2]     = acc0 * inv + __ldg(&b2[lane * 2]);
        out[(size_t)w * 40 + lane * 2 + 1] = acc1 * inv + __ldg(&b2[lane * 2 + 1]);
    }
}

// ---------------- launch ----------------
extern "C" void kernel_launch(void* const* d_in, const int* in_sizes, int n_in,
                              void* d_out, int out_size) {
    const float* x    = (const float*)d_in[0];
    const void*  edge = (const void*)d_in[1];
    const float* W1   = (const float*)d_in[2];
    const float* as1  = (const float*)d_in[3];
    const float* ad1  = (const float*)d_in[4];
    const float* b1   = (const float*)d_in[5];
    const float* W2   = (const float*)d_in[6];
    const float* as2  = (const float*)d_in[7];
    const float* ad2  = (const float*)d_in[8];
    const float* b2   = (const float*)d_in[9];
    float* out = (float*)d_out;

    int N  = in_sizes[0] / 256;
    int E  = in_sizes[1] / 2;
    int ET = E + N;

    __nv_bfloat16 *wh, *wl;
    cudaGetSymbolAddress((void**)&wh, g_wh);
    cudaGetSymbolAddress((void**)&wl, g_wl);

    // launch idx: 0 split W1; 1 detect+zero; 2 split_w2; 3 gemm1_tc (profiled slot)
    k_split<<<(65536 + 255) / 256, 256>>>(W1, wh, wl, 65536);
    k_detect<<<(N + 255) / 256, 256>>>((const int*)edge, E, N);
    k_split_w2<<<(256 * 64 + 255) / 256, 256>>>(W2);
    k_gemm1_tc<<<dim3(2, (N + 127) / 128), 256>>>(x, N, as1, ad1);

    // CSR build
    k_count<<<(ET + 255) / 256, 256>>>(edge, E, N);
    k_scan_fused<<<1, 1024>>>(N);
    k_scatter<<<(ET + 255) / 256, 256>>>(edge, E, N);

    // Layer 1
    int warpGrid = (N * 32 + 255) / 256;
    k_agg1<<<warpGrid, 256>>>(b1, N);

    // Layer 2
    k_gemm2_tc<<<(N + 127) / 128, 256>>>(N);
    k_attn2<<<warpGrid, 256>>>(as2, ad2, N);
    k_agg2<<<warpGrid, 256>>>(b2, out, N);
}

// round 13
// speedup vs baseline: 1.6831x; 1.0220x over previous
#include <cuda_runtime.h>
#include <cuda_bf16.h>
#include <cuda_fp16.h>
#include <cstdint>
#include <math.h>

// ---------------- static scratch (no allocs allowed) ----------------
#define NMAX 50176
#define EMAX 1700000

__device__ __half g_h1f[NMAX * 256];          // x @ W1 (fp16, for agg1 gather)
__device__ __nv_bfloat16 g_h1ah[NMAX * 256], g_h1al[NMAX * 256]; // layer1 out, bf16 split
__device__ __half g_h2f[NMAX * 40];           // fp16 for agg2 gather
__device__ float g_as1[NMAX * 4], g_ad1[NMAX * 4];
__device__ float g_as2[NMAX],     g_ad2[NMAX];
__device__ int   g_deg[NMAX], g_off[NMAX + 1], g_cur[NMAX];
__device__ int   g_csr[EMAX];
__device__ int   g_is64;
// bf16 split operands for tensor-core GEMMs
__device__ __nv_bfloat16 g_wh[256 * 256],  g_wl[256 * 256];
__device__ __nv_bfloat16 g_w2h[256 * 64],  g_w2l[256 * 64];   // W2 padded 40->64

// ---------------- PTX helpers ----------------
__device__ __forceinline__ unsigned smem_u32(const void* p) {
    return (unsigned)__cvta_generic_to_shared(p);
}
__device__ __forceinline__ void ldsm_x4(unsigned addr, unsigned& r0, unsigned& r1, unsigned& r2, unsigned& r3) {
    asm volatile("ldmatrix.sync.aligned.m8n8.x4.shared.b16 {%0,%1,%2,%3},[%4];"
                 : "=r"(r0), "=r"(r1), "=r"(r2), "=r"(r3) : "r"(addr));
}
__device__ __forceinline__ void ldsm_x4t(unsigned addr, unsigned& r0, unsigned& r1, unsigned& r2, unsigned& r3) {
    asm volatile("ldmatrix.sync.aligned.m8n8.x4.trans.shared.b16 {%0,%1,%2,%3},[%4];"
                 : "=r"(r0), "=r"(r1), "=r"(r2), "=r"(r3) : "r"(addr));
}
__device__ __forceinline__ void mma_bf16(float* c, unsigned a0, unsigned a1, unsigned a2, unsigned a3,
                                         unsigned b0, unsigned b1) {
    asm volatile("mma.sync.aligned.m16n8k16.row.col.f32.bf16.bf16.f32 "
                 "{%0,%1,%2,%3},{%4,%5,%6,%7},{%8,%9},{%0,%1,%2,%3};"
                 : "+f"(c[0]), "+f"(c[1]), "+f"(c[2]), "+f"(c[3])
                 : "r"(a0), "r"(a1), "r"(a2), "r"(a3), "r"(b0), "r"(b1));
}

// ---------------- bf16 split conversion (W1 only) ----------------
__global__ void k_split(const float* __restrict__ src, __nv_bfloat16* __restrict__ hi,
                        __nv_bfloat16* __restrict__ lo, int n) {
    int i = blockIdx.x * blockDim.x + threadIdx.x;
    if (i >= n) return;
    float v = src[i];
    __nv_bfloat16 h = __float2bfloat16(v);
    hi[i] = h;
    lo[i] = __float2bfloat16(v - __bfloat162float(h));
}

__global__ void k_split_w2(const float* __restrict__ W2) {
    int i = blockIdx.x * blockDim.x + threadIdx.x;   // over 256*64
    if (i >= 256 * 64) return;
    int r = i >> 6, c = i & 63;
    float v = (c < 40) ? W2[r * 40 + c] : 0.f;
    __nv_bfloat16 h = __float2bfloat16(v);
    g_w2h[i] = h;
    g_w2l[i] = __float2bfloat16(v - __bfloat162float(h));
}

// ---------------- edge dtype detection + zero deg/as2/ad2 (fused) ----------------
__global__ void k_detect(const int* __restrict__ e32, int E, int N) {
    int i = blockIdx.x * blockDim.x + threadIdx.x;
    if (i < N) {
        g_deg[i] = 0;
        g_as2[i] = 0.f;
        g_ad2[i] = 0.f;
    }
    if (blockIdx.x == 0 && threadIdx.x < 32) {
        int lane = threadIdx.x;
        int nz = 0;
        for (int k = lane; k < 64; k += 32)
            if (k < E) nz |= (e32[2 * k + 1] != 0);
        unsigned b = __ballot_sync(0xffffffffu, nz);
        if (lane == 0) g_is64 = (b == 0u);
    }
}

__device__ __forceinline__ int edge_at(const void* edge, int is64, long long idx) {
    if (is64) return (int)((const long long*)edge)[idx];
    return ((const int*)edge)[idx];
}

// ---------------- CSR build ----------------
__global__ void k_count(const void* __restrict__ edge, int E, int N) {
    int e = blockIdx.x * blockDim.x + threadIdx.x;
    int ET = E + N;
    if (e >= ET) return;
    int is64 = g_is64;
    int dst = (e < E) ? edge_at(edge, is64, (long long)E + e) : (e - E);
    atomicAdd(&g_deg[dst], 1);
}

__global__ void __launch_bounds__(1024) k_scan_fused(int N) {
    __shared__ int s[1024];
    int t = threadIdx.x;
    int chunk = (N + 1023) >> 10;
    int base = t * chunk;
    int sum = 0;
    for (int i = 0; i < chunk; i++) {
        int idx = base + i;
        if (idx < N) sum += g_deg[idx];
    }
    s[t] = sum;
    __syncthreads();
    for (int o = 1; o < 1024; o <<= 1) {
        int v = (t >= o) ? s[t - o] : 0;
        __syncthreads();
        s[t] += v;
        __syncthreads();
    }
    int run = s[t] - sum;
    for (int i = 0; i < chunk; i++) {
        int idx = base + i;
        if (idx < N) {
            g_off[idx] = run;
            g_cur[idx] = run;
            run += g_deg[idx];
        }
    }
    if (t == 1023) g_off[N] = s[1023];
}

__global__ void k_scatter(const void* __restrict__ edge, int E, int N) {
    int e = blockIdx.x * blockDim.x + threadIdx.x;
    int ET = E + N;
    if (e >= ET) return;
    int src, dst;
    if (e < E) {
        int is64 = g_is64;
        src = edge_at(edge, is64, e);
        dst = edge_at(edge, is64, (long long)E + e);
    } else {
        src = dst = e - E;
    }
    int pos = atomicAdd(&g_cur[dst], 1);
    g_csr[pos] = src;
}

// ---------------- GEMM1: x fp32 loaded directly, split in-kernel; fused attn1 ----------------
#define LDA 40
#define LDB1 136
__global__ void __launch_bounds__(256, 2) k_gemm1_tc(const float* __restrict__ X, int M,
        const float* __restrict__ att_s, const float* __restrict__ att_d) {
    __shared__ __nv_bfloat16 Ah[128 * LDA], Al[128 * LDA];
    __shared__ __nv_bfloat16 Bh[32 * LDB1], Bl[32 * LDB1];
    int tid = threadIdx.x;
    int warp = tid >> 5, lane = tid & 31;
    int wm = warp & 3, wn = warp >> 2;
    int row0 = blockIdx.y * 128, col0 = blockIdx.x * 128;

    float acc[2][8][4];
#pragma unroll
    for (int mi = 0; mi < 2; mi++)
#pragma unroll
        for (int ni = 0; ni < 8; ni++)
#pragma unroll
            for (int k = 0; k < 4; k++) acc[mi][ni][k] = 0.f;

    int lrow = lane & 15, lcb = lane >> 4;

    for (int kt = 0; kt < 256; kt += 32) {
        // A tile 128x32: load fp32, split to bf16 hi/lo in-register
#pragma unroll
        for (int i = 0; i < 2; i++) {
            int v = tid + i * 256;
            int r = v >> 2, cv = (v & 3) * 8;
            int gr = row0 + r;
            float4 f0 = make_float4(0.f, 0.f, 0.f, 0.f), f1 = f0;
            if (gr < M) {
                f0 = *(const float4*)&X[(size_t)gr * 256 + kt + cv];
                f1 = *(const float4*)&X[(size_t)gr * 256 + kt + cv + 4];
            }
            float fv[8] = {f0.x, f0.y, f0.z, f0.w, f1.x, f1.y, f1.z, f1.w};
            __nv_bfloat16 hb[8], lb[8];
#pragma unroll
            for (int k = 0; k < 8; k++) {
                hb[k] = __float2bfloat16(fv[k]);
                lb[k] = __float2bfloat16(fv[k] - __bfloat162float(hb[k]));
            }
            *(uint4*)&Ah[r * LDA + cv] = *(const uint4*)hb;
            *(uint4*)&Al[r * LDA + cv] = *(const uint4*)lb;
        }
        // B tile 32x128 hi+lo
#pragma unroll
        for (int i = 0; i < 2; i++) {
            int v = tid + i * 256;
            int r = v >> 4, cv = (v & 15) * 8;
            *(uint4*)&Bh[r * LDB1 + cv] = *(const uint4*)&g_wh[(size_t)(kt + r) * 256 + col0 + cv];
            *(uint4*)&Bl[r * LDB1 + cv] = *(const uint4*)&g_wl[(size_t)(kt + r) * 256 + col0 + cv];
        }
        __syncthreads();

#pragma unroll
        for (int ks = 0; ks < 32; ks += 16) {
            unsigned ah[2][4], al[2][4], bh[4][4], bl[4][4];
#pragma unroll
            for (int mi = 0; mi < 2; mi++) {
                unsigned ad = smem_u32(&Ah[(wm * 32 + mi * 16 + lrow) * LDA + ks + lcb * 8]);
                ldsm_x4(ad, ah[mi][0], ah[mi][1], ah[mi][2], ah[mi][3]);
                unsigned ad2 = smem_u32(&Al[(wm * 32 + mi * 16 + lrow) * LDA + ks + lcb * 8]);
                ldsm_x4(ad2, al[mi][0], al[mi][1], al[mi][2], al[mi][3]);
            }
#pragma unroll
            for (int nj = 0; nj < 4; nj++) {
                unsigned bd = smem_u32(&Bh[(ks + lrow) * LDB1 + wn * 64 + nj * 16 + lcb * 8]);
                ldsm_x4t(bd, bh[nj][0], bh[nj][1], bh[nj][2], bh[nj][3]);
                unsigned bd2 = smem_u32(&Bl[(ks + lrow) * LDB1 + wn * 64 + nj * 16 + lcb * 8]);
                ldsm_x4t(bd2, bl[nj][0], bl[nj][1], bl[nj][2], bl[nj][3]);
            }
#pragma unroll
            for (int mi = 0; mi < 2; mi++)
#pragma unroll
                for (int ni = 0; ni < 8; ni++) {
                    int nj = ni >> 1, s2 = (ni & 1) * 2;
                    mma_bf16(acc[mi][ni], ah[mi][0], ah[mi][1], ah[mi][2], ah[mi][3],
                             bh[nj][s2], bh[nj][s2 + 1]);
                    mma_bf16(acc[mi][ni], ah[mi][0], ah[mi][1], ah[mi][2], ah[mi][3],
                             bl[nj][s2], bl[nj][s2 + 1]);
                    mma_bf16(acc[mi][ni], al[mi][0], al[mi][1], al[mi][2], al[mi][3],
                             bh[nj][s2], bh[nj][s2 + 1]);
                }
        }
        __syncthreads();
    }

    // epilogue: fp16 stores + fused attn1 (warp column = one head)
    int tr = lane >> 2, tc = (lane & 3) * 2;
    int head = blockIdx.x * 2 + wn;
#pragma unroll
    for (int mi = 0; mi < 2; mi++) {
        float ps0 = 0.f, pd0 = 0.f, ps1 = 0.f, pd1 = 0.f;
#pragma unroll
        for (int ni = 0; ni < 8; ni++) {
            int r = row0 + wm * 32 + mi * 16 + tr;
            int c = col0 + wn * 64 + ni * 8 + tc;
            if (r < M)
                *(__half2*)&g_h1f[(size_t)r * 256 + c] = __floats2half2_rn(acc[mi][ni][0], acc[mi][ni][1]);
            if (r + 8 < M)
                *(__half2*)&g_h1f[(size_t)(r + 8) * 256 + c] = __floats2half2_rn(acc[mi][ni][2], acc[mi][ni][3]);
            float s0 = __ldg(&att_s[c]), s1 = __ldg(&att_s[c + 1]);
            float d0 = __ldg(&att_d[c]), d1 = __ldg(&att_d[c + 1]);
            ps0 = fmaf(acc[mi][ni][0], s0, ps0); ps0 = fmaf(acc[mi][ni][1], s1, ps0);
            pd0 = fmaf(acc[mi][ni][0], d0, pd0); pd0 = fmaf(acc[mi][ni][1], d1, pd0);
            ps1 = fmaf(acc[mi][ni][2], s0, ps1); ps1 = fmaf(acc[mi][ni][3], s1, ps1);
            pd1 = fmaf(acc[mi][ni][2], d0, pd1); pd1 = fmaf(acc[mi][ni][3], d1, pd1);
        }
        ps0 += __shfl_xor_sync(0xffffffffu, ps0, 1); ps0 += __shfl_xor_sync(0xffffffffu, ps0, 2);
        pd0 += __shfl_xor_sync(0xffffffffu, pd0, 1); pd0 += __shfl_xor_sync(0xffffffffu, pd0, 2);
        ps1 += __shfl_xor_sync(0xffffffffu, ps1, 1); ps1 += __shfl_xor_sync(0xffffffffu, ps1, 2);
        pd1 += __shfl_xor_sync(0xffffffffu, pd1, 1); pd1 += __shfl_xor_sync(0xffffffffu, pd1, 2);
        if ((lane & 3) == 0) {
            int r0 = row0 + wm * 32 + mi * 16 + tr;
            if (r0 < M)     { g_as1[r0 * 4 + head] = ps0; g_ad1[r0 * 4 + head] = pd0; }
            if (r0 + 8 < M) { g_as1[(r0 + 8) * 4 + head] = ps1; g_ad1[(r0 + 8) * 4 + head] = pd1; }
        }
    }
}

// ---------------- GEMM2 (tensor core): h2 = h1a @ W2pad, fused attn2 ----------------
#define LDB 72
__global__ void __launch_bounds__(256) k_gemm2_tc(int M,
        const float* __restrict__ att_s, const float* __restrict__ att_d) {
    __shared__ __nv_bfloat16 Ah[128 * LDA], Al[128 * LDA];
    __shared__ __nv_bfloat16 Bh[32 * LDB],  Bl[32 * LDB];
    int tid = threadIdx.x;
    int warp = tid >> 5, lane = tid & 31;
    int wm = warp & 3, wn = warp >> 2;
    int row0 = blockIdx.x * 128;

    float acc[2][4][4];
#pragma unroll
    for (int mi = 0; mi < 2; mi++)
#pragma unroll
        for (int ni = 0; ni < 4; ni++)
#pragma unroll
            for (int k = 0; k < 4; k++) acc[mi][ni][k] = 0.f;

    int lrow = lane & 15, lcb = lane >> 4;

    for (int kt = 0; kt < 256; kt += 32) {
#pragma unroll
        for (int i = 0; i < 2; i++) {
            int v = tid + i * 256;
            int r = v >> 2, cv = (v & 3) * 8;
            int gr = row0 + r;
            uint4 vh, vl;
            if (gr < M) {
                vh = *(const uint4*)&g_h1ah[(size_t)gr * 256 + kt + cv];
                vl = *(const uint4*)&g_h1al[(size_t)gr * 256 + kt + cv];
            } else { vh = make_uint4(0,0,0,0); vl = vh; }
            *(uint4*)&Ah[r * LDA + cv] = vh;
            *(uint4*)&Al[r * LDA + cv] = vl;
        }
        {
            int r = tid >> 3, cv = (tid & 7) * 8;
            *(uint4*)&Bh[r * LDB + cv] = *(const uint4*)&g_w2h[(size_t)(kt + r) * 64 + cv];
            *(uint4*)&Bl[r * LDB + cv] = *(const uint4*)&g_w2l[(size_t)(kt + r) * 64 + cv];
        }
        __syncthreads();

#pragma unroll
        for (int ks = 0; ks < 32; ks += 16) {
            unsigned ah[2][4], al[2][4], bh[2][4], bl[2][4];
#pragma unroll
            for (int mi = 0; mi < 2; mi++) {
                unsigned ad = smem_u32(&Ah[(wm * 32 + mi * 16 + lrow) * LDA + ks + lcb * 8]);
                ldsm_x4(ad, ah[mi][0], ah[mi][1], ah[mi][2], ah[mi][3]);
                unsigned ad2 = smem_u32(&Al[(wm * 32 + mi * 16 + lrow) * LDA + ks + lcb * 8]);
                ldsm_x4(ad2, al[mi][0], al[mi][1], al[mi][2], al[mi][3]);
            }
#pragma unroll
            for (int nj = 0; nj < 2; nj++) {
                unsigned bd = smem_u32(&Bh[(ks + lrow) * LDB + wn * 32 + nj * 16 + lcb * 8]);
                ldsm_x4t(bd, bh[nj][0], bh[nj][1], bh[nj][2], bh[nj][3]);
                unsigned bd2 = smem_u32(&Bl[(ks + lrow) * LDB + wn * 32 + nj * 16 + lcb * 8]);
                ldsm_x4t(bd2, bl[nj][0], bl[nj][1], bl[nj][2], bl[nj][3]);
            }
#pragma unroll
            for (int mi = 0; mi < 2; mi++)
#pragma unroll
                for (int ni = 0; ni < 4; ni++) {
                    int nj = ni >> 1, s2 = (ni & 1) * 2;
                    mma_bf16(acc[mi][ni], ah[mi][0], ah[mi][1], ah[mi][2], ah[mi][3],
                             bh[nj][s2], bh[nj][s2 + 1]);
                    mma_bf16(acc[mi][ni], ah[mi][0], ah[mi][1], ah[mi][2], ah[mi][3],
                             bl[nj][s2], bl[nj][s2 + 1]);
                    mma_bf16(acc[mi][ni], al[mi][0], al[mi][1], al[mi][2], al[mi][3],
                             bh[nj][s2], bh[nj][s2 + 1]);
                }
        }
        __syncthreads();
    }

    // epilogue: fp16 stores + fused attn2 partials (2 warps per row -> atomicAdd, commutative => deterministic)
    int tr = lane >> 2, tc = (lane & 3) * 2;
#pragma unroll
    for (int mi = 0; mi < 2; mi++) {
        float ps0 = 0.f, pd0 = 0.f, ps1 = 0.f, pd1 = 0.f;
#pragma unroll
        for (int ni = 0; ni < 4; ni++) {
            int r = row0 + wm * 32 + mi * 16 + tr;
            int c = wn * 32 + ni * 8 + tc;
            if (c < 40) {
                if (r < M)
                    *(__half2*)&g_h2f[(size_t)r * 40 + c] = __floats2half2_rn(acc[mi][ni][0], acc[mi][ni][1]);
                if (r + 8 < M)
                    *(__half2*)&g_h2f[(size_t)(r + 8) * 40 + c] = __floats2half2_rn(acc[mi][ni][2], acc[mi][ni][3]);
                float s0 = __ldg(&att_s[c]), s1 = __ldg(&att_s[c + 1]);
                float d0 = __ldg(&att_d[c]), d1 = __ldg(&att_d[c + 1]);
                ps0 = fmaf(acc[mi][ni][0], s0, ps0); ps0 = fmaf(acc[mi][ni][1], s1, ps0);
                pd0 = fmaf(acc[mi][ni][0], d0, pd0); pd0 = fmaf(acc[mi][ni][1], d1, pd0);
                ps1 = fmaf(acc[mi][ni][2], s0, ps1); ps1 = fmaf(acc[mi][ni][3], s1, ps1);
                pd1 = fmaf(acc[mi][ni][2], d0, pd1); pd1 = fmaf(acc[mi][ni][3], d1, pd1);
            }
        }
        ps0 += __shfl_xor_sync(0xffffffffu, ps0, 1); ps0 += __shfl_xor_sync(0xffffffffu, ps0, 2);
        pd0 += __shfl_xor_sync(0xffffffffu, pd0, 1); pd0 += __shfl_xor_sync(0xffffffffu, pd0, 2);
        ps1 += __shfl_xor_sync(0xffffffffu, ps1, 1); ps1 += __shfl_xor_sync(0xffffffffu, ps1, 2);
        pd1 += __shfl_xor_sync(0xffffffffu, pd1, 1); pd1 += __shfl_xor_sync(0xffffffffu, pd1, 2);
        if ((lane & 3) == 0) {
            int r0 = row0 + wm * 32 + mi * 16 + tr;
            if (r0 < M)     { atomicAdd(&g_as2[r0], ps0); atomicAdd(&g_ad2[r0], pd0); }
            if (r0 + 8 < M) { atomicAdd(&g_as2[r0 + 8], ps1); atomicAdd(&g_ad2[r0 + 8], pd1); }
        }
    }
}

// ---------------- agg1: inline edge weights, fp16 gather, + bias + ELU, bf16-split out ----------------
__global__ void k_agg1(const float* __restrict__ bias, int M) {
    int w = (blockIdx.x * blockDim.x + threadIdx.x) >> 5;
    int lane = threadIdx.x & 31;
    if (w >= M) return;
    int start = g_off[w], end = g_off[w + 1];
    int hh = lane >> 3;
    int c0 = lane * 8;
    float4 adv = *(const float4*)&g_ad1[w * 4];
    float adh = (hh == 0) ? adv.x : (hh == 1) ? adv.y : (hh == 2) ? adv.z : adv.w;

    float acc[8] = {0.f, 0.f, 0.f, 0.f, 0.f, 0.f, 0.f, 0.f};
    float denom = 0.f;
    int j = start;
    for (; j + 1 < end; j += 2) {
        int s0 = g_csr[j], s1 = g_csr[j + 1];
        float e0 = g_as1[s0 * 4 + hh] + adh;
        float e1 = g_as1[s1 * 4 + hh] + adh;
        e0 = e0 > 0.f ? e0 : 0.2f * e0;
        e1 = e1 > 0.f ? e1 : 0.2f * e1;
        float w0 = __expf(e0), w1 = __expf(e1);
        uint4 q0 = *(const uint4*)&g_h1f[(size_t)s0 * 256 + c0];
        uint4 q1 = *(const uint4*)&g_h1f[(size_t)s1 * 256 + c0];
        denom += w0 + w1;
        const __half2* a = (const __half2*)&q0;
        const __half2* b = (const __half2*)&q1;
#pragma unroll
        for (int k = 0; k < 4; k++) {
            float2 fa = __half22float2(a[k]);
            float2 fb = __half22float2(b[k]);
            acc[2*k]   = fmaf(w0, fa.x, acc[2*k]);   acc[2*k]   = fmaf(w1, fb.x, acc[2*k]);
            acc[2*k+1] = fmaf(w0, fa.y, acc[2*k+1]); acc[2*k+1] = fmaf(w1, fb.y, acc[2*k+1]);
        }
    }
    if (j < end) {
        int s0 = g_csr[j];
        float e0 = g_as1[s0 * 4 + hh] + adh;
        e0 = e0 > 0.f ? e0 : 0.2f * e0;
        float w0 = __expf(e0);
        uint4 q0 = *(const uint4*)&g_h1f[(size_t)s0 * 256 + c0];
        denom += w0;
        const __half2* a = (const __half2*)&q0;
#pragma unroll
        for (int k = 0; k < 4; k++) {
            float2 fa = __half22float2(a[k]);
            acc[2*k]   = fmaf(w0, fa.x, acc[2*k]);
            acc[2*k+1] = fmaf(w0, fa.y, acc[2*k+1]);
        }
    }
    float inv = 1.f / denom;
    __nv_bfloat16 hi8[8], lo8[8];
#pragma unroll
    for (int k = 0; k < 8; k++) {
        float v = acc[k] * inv + bias[c0 + k];
        v = v > 0.f ? v : (__expf(v) - 1.f);   // ELU
        __nv_bfloat16 h = __float2bfloat16(v);
        hi8[k] = h;
        lo8[k] = __float2bfloat16(v - __bfloat162float(h));
    }
    *(uint4*)&g_h1ah[(size_t)w * 256 + c0] = *(const uint4*)hi8;
    *(uint4*)&g_h1al[(size_t)w * 256 + c0] = *(const uint4*)lo8;
}

// ---------------- agg2: inline edge weights, fp16 gather, final output ----------------
__global__ void k_agg2(const float* __restrict__ b2, float* __restrict__ out, int M) {
    int w = (blockIdx.x * blockDim.x + threadIdx.x) >> 5;
    int lane = threadIdx.x & 31;
    if (w >= M) return;
    int start = g_off[w], end = g_off[w + 1];
    float adv = g_ad2[w];
    bool val = lane < 20;
    float denom = 0.f, acc0 = 0.f, acc1 = 0.f;
    int j = start;
    for (; j + 1 < end; j += 2) {
        int s0 = g_csr[j], s1 = g_csr[j + 1];
        float e0 = g_as2[s0] + adv;
        float e1 = g_as2[s1] + adv;
        e0 = e0 > 0.f ? e0 : 0.2f * e0;
        e1 = e1 > 0.f ? e1 : 0.2f * e1;
        float w0 = __expf(e0), w1 = __expf(e1);
        float2 f0 = make_float2(0.f, 0.f), f1 = f0;
        if (val) {
            f0 = __half22float2(*(const __half2*)&g_h2f[(size_t)s0 * 40 + lane * 2]);
            f1 = __half22float2(*(const __half2*)&g_h2f[(size_t)s1 * 40 + lane * 2]);
        }
        denom += w0 + w1;
        acc0 = fmaf(w0, f0.x, acc0); acc0 = fmaf(w1, f1.x, acc0);
        acc1 = fmaf(w0, f0.y, acc1); acc1 = fmaf(w1, f1.y, acc1);
    }
    if (j < end) {
        int s0 = g_csr[j];
        float e0 = g_as2[s0] + adv;
        e0 = e0 > 0.f ? e0 : 0.2f * e0;
        float w0 = __expf(e0);
        float2 f0 = make_float2(0.f, 0.f);
        if (val) f0 = __half22float2(*(const __half2*)&g_h2f[(size_t)s0 * 40 + lane * 2]);
        denom += w0;
        acc0 = fmaf(w0, f0.x, acc0);
        acc1 = fmaf(w0, f0.y, acc1);
    }
    float inv = 1.f / denom;
    if (val) {
        out[(size_t)w * 40 + lane * 2]     = acc0 * inv + __ldg(&b2[lane * 2]);
        out[(size_t)w * 40 + lane * 2 + 1] = acc1 * inv + __ldg(&b2[lane * 2 + 1]);
    }
}

// ---------------- launch ----------------
extern "C" void kernel_launch(void* const* d_in, const int* in_sizes, int n_in,
                              void* d_out, int out_size) {
    const float* x    = (const float*)d_in[0];
    const void*  edge = (const void*)d_in[1];
    const float* W1   = (const float*)d_in[2];
    const float* as1  = (const float*)d_in[3];
    const float* ad1  = (const float*)d_in[4];
    const float* b1   = (const float*)d_in[5];
    const float* W2   = (const float*)d_in[6];
    const float* as2  = (const float*)d_in[7];
    const float* ad2  = (const float*)d_in[8];
    const float* b2   = (const float*)d_in[9];
    float* out = (float*)d_out;

    int N  = in_sizes[0] / 256;
    int E  = in_sizes[1] / 2;
    int ET = E + N;

    __nv_bfloat16 *wh, *wl;
    cudaGetSymbolAddress((void**)&wh, g_wh);
    cudaGetSymbolAddress((void**)&wl, g_wl);

    // launch idx: 0 split W1; 1 detect+zero; 2 split_w2; 3 gemm1_tc (profiled slot)
    k_split<<<(65536 + 255) / 256, 256>>>(W1, wh, wl, 65536);
    k_detect<<<(N + 255) / 256, 256>>>((const int*)edge, E, N);
    k_split_w2<<<(256 * 64 + 255) / 256, 256>>>(W2);
    k_gemm1_tc<<<dim3(2, (N + 127) / 128), 256>>>(x, N, as1, ad1);

    // CSR build
    k_count<<<(ET + 255) / 256, 256>>>(edge, E, N);
    k_scan_fused<<<1, 1024>>>(N);
    k_scatter<<<(ET + 255) / 256, 256>>>(edge, E, N);

    // Layer 1
    int warpGrid = (N * 32 + 255) / 256;
    k_agg1<<<warpGrid, 256>>>(b1, N);

    // Layer 2
    k_gemm2_tc<<<(N + 127) / 128, 256>>>(N, as2, ad2);
    k_agg2<<<warpGrid, 256>>>(b2, out, N);
}